// round 8
// baseline (speedup 1.0000x reference)
#include <cuda_runtime.h>
#include <math.h>

#define T_ 30
#define C_ 512
#define N_ 784
#define K_ 64
#define KD_ (K_ * C_)   // 32768
#define NB_ 13          // assign n-tiles per t

// ---------------- device scratch ----------------
__device__ float g_aT[T_ * N_ * K_];        // a' = softmax * invn, [t][n][k]
__device__ float g_asump[T_ * NB_ * K_];    // per-block partial asum
__device__ float g_vladA[T_ * K_ * C_];     // partial s0 -> normalized vlad
__device__ float g_vladB[T_ * K_ * C_];     // partial s1
__device__ float g_gssp[T_ * K_];           // per-row sumsq (post-intra-norm)

typedef unsigned long long u64;
__device__ __forceinline__ u64 pk2(float lo, float hi) {
    u64 r;
    asm("mov.b64 %0, {%1, %2};" : "=l"(r) : "f"(lo), "f"(hi));
    return r;
}
__device__ __forceinline__ void upk2(u64 v, float& lo, float& hi) {
    asm("mov.b64 {%0, %1}, %2;" : "=f"(lo), "=f"(hi) : "l"(v));
}
__device__ __forceinline__ void fma2(u64& d, u64 a, u64 b) {
    asm("fma.rn.f32x2 %0, %1, %2, %0;" : "+l"(d) : "l"(a), "l"(b));
}

// ---------------- pass 1: invnorm + logits GEMM + softmax -> aT', asum partials ----------------
// grid (13, T), block 128.  K=64 x N=64 tile; W transposed in-fill; x stored duplicated for LDS.64.
__global__ __launch_bounds__(128) void assign_kernel(
    const float* __restrict__ x, const float* __restrict__ w,
    const float* __restrict__ bias)
{
    const int t   = blockIdx.y;
    const int n0  = blockIdx.x * 64;
    const int tid = threadIdx.x;
    const int tyk = tid >> 4;          // 0..7  -> k0 = tyk*8
    const int txn = tid & 15;          // 0..15 -> nl = txn*4
    const int k0  = tyk * 8;
    const int nl  = txn * 4;

    __shared__ float Ws[2][2048];      // [buf][ci][k]
    __shared__ float Xd[2][4096];      // [buf] ci*128 + j*32 + txn*2 (+dup)
    __shared__ float red[128];
    __shared__ float4 red4[4][16];
    __shared__ float invn_s[64];
    __shared__ float rinvs[64];
    __shared__ float bsm[64];
    float* Ls = Xd[0];                 // alias: logits live after GEMM loop (safe: see sync order)

    if (tid < 64) bsm[tid] = bias[tid];

    u64 acc[4][4];
#pragma unroll
    for (int p = 0; p < 4; p++)
#pragma unroll
        for (int j = 0; j < 4; j++) acc[p][j] = 0ull;

    float4 ss4 = make_float4(0.f, 0.f, 0.f, 0.f);
    const float* xt = x + (size_t)t * C_ * N_;

    // ---- prologue: chunk 0 -> buffer 0 ----
#pragma unroll
    for (int j = 0; j < 4; j++) {
        int e = tid + j * 128;                    // [0,512)
        // W transpose: Ws[ci][k] = w[k][cc*32+ci]
        int kk = e & 63, ci0 = (e >> 6) * 4;
        float4 w4 = *(const float4*)&w[(size_t)kk * C_ + ci0];
        Ws[0][(ci0 + 0) * 64 + kk] = w4.x;
        Ws[0][(ci0 + 1) * 64 + kk] = w4.y;
        Ws[0][(ci0 + 2) * 64 + kk] = w4.z;
        Ws[0][(ci0 + 3) * 64 + kk] = w4.w;
        // X: dup-pair store
        int ci = e >> 4, c4 = e & 15;
        int n  = n0 + c4 * 4;
        float4 v = make_float4(0.f, 0.f, 0.f, 0.f);
        if (n < N_) v = *(const float4*)&xt[(size_t)ci * N_ + n];
        ss4.x += v.x * v.x; ss4.y += v.y * v.y; ss4.z += v.z * v.z; ss4.w += v.w * v.w;
        float* b0 = &Xd[0][ci * 128 + c4 * 2];
        *(u64*)(b0 +  0) = pk2(v.x, v.x);
        *(u64*)(b0 + 32) = pk2(v.y, v.y);
        *(u64*)(b0 + 64) = pk2(v.z, v.z);
        *(u64*)(b0 + 96) = pk2(v.w, v.w);
    }
    __syncthreads();

    for (int cc = 0; cc < 16; cc++) {
        const int p = cc & 1;
        float4 wq[4], xq[4];
        if (cc < 15) {
#pragma unroll
            for (int j = 0; j < 4; j++) {
                int e = tid + j * 128;
                int kk = e & 63, ci0 = (e >> 6) * 4;
                wq[j] = *(const float4*)&w[(size_t)kk * C_ + (cc + 1) * 32 + ci0];
                int ci = e >> 4, c4 = e & 15;
                int n  = n0 + c4 * 4;
                xq[j] = make_float4(0.f, 0.f, 0.f, 0.f);
                if (n < N_) xq[j] = *(const float4*)&xt[(size_t)((cc + 1) * 32 + ci) * N_ + n];
                ss4.x += xq[j].x * xq[j].x; ss4.y += xq[j].y * xq[j].y;
                ss4.z += xq[j].z * xq[j].z; ss4.w += xq[j].w * xq[j].w;
            }
        }

        const float* Wp = Ws[p];
        const float* Xp = Xd[p];
#pragma unroll
        for (int ci = 0; ci < 32; ci++) {
            u64 wp0 = *(const u64*)&Wp[ci * 64 + k0 + 0];
            u64 wp1 = *(const u64*)&Wp[ci * 64 + k0 + 2];
            u64 wp2 = *(const u64*)&Wp[ci * 64 + k0 + 4];
            u64 wp3 = *(const u64*)&Wp[ci * 64 + k0 + 6];
            u64 xd0 = *(const u64*)&Xp[ci * 128 +  0 + txn * 2];
            u64 xd1 = *(const u64*)&Xp[ci * 128 + 32 + txn * 2];
            u64 xd2 = *(const u64*)&Xp[ci * 128 + 64 + txn * 2];
            u64 xd3 = *(const u64*)&Xp[ci * 128 + 96 + txn * 2];
            fma2(acc[0][0], wp0, xd0); fma2(acc[0][1], wp0, xd1);
            fma2(acc[0][2], wp0, xd2); fma2(acc[0][3], wp0, xd3);
            fma2(acc[1][0], wp1, xd0); fma2(acc[1][1], wp1, xd1);
            fma2(acc[1][2], wp1, xd2); fma2(acc[1][3], wp1, xd3);
            fma2(acc[2][0], wp2, xd0); fma2(acc[2][1], wp2, xd1);
            fma2(acc[2][2], wp2, xd2); fma2(acc[2][3], wp2, xd3);
            fma2(acc[3][0], wp3, xd0); fma2(acc[3][1], wp3, xd1);
            fma2(acc[3][2], wp3, xd2); fma2(acc[3][3], wp3, xd3);
        }

        if (cc < 15) {
            const int q = p ^ 1;
#pragma unroll
            for (int j = 0; j < 4; j++) {
                int e = tid + j * 128;
                int kk = e & 63, ci0 = (e >> 6) * 4;
                Ws[q][(ci0 + 0) * 64 + kk] = wq[j].x;
                Ws[q][(ci0 + 1) * 64 + kk] = wq[j].y;
                Ws[q][(ci0 + 2) * 64 + kk] = wq[j].z;
                Ws[q][(ci0 + 3) * 64 + kk] = wq[j].w;
                int ci = e >> 4, c4 = e & 15;
                float* b0 = &Xd[q][ci * 128 + c4 * 2];
                *(u64*)(b0 +  0) = pk2(xq[j].x, xq[j].x);
                *(u64*)(b0 + 32) = pk2(xq[j].y, xq[j].y);
                *(u64*)(b0 + 64) = pk2(xq[j].z, xq[j].z);
                *(u64*)(b0 + 96) = pk2(xq[j].w, xq[j].w);
            }
            __syncthreads();
        }
    }

    // ---- sumsq reduction ----
    ss4.x += __shfl_xor_sync(0xffffffff, ss4.x, 16);
    ss4.y += __shfl_xor_sync(0xffffffff, ss4.y, 16);
    ss4.z += __shfl_xor_sync(0xffffffff, ss4.z, 16);
    ss4.w += __shfl_xor_sync(0xffffffff, ss4.w, 16);
    if ((tid & 31) < 16) red4[tid >> 5][tid & 15] = ss4;
    __syncthreads();          // all warps done with GEMM -> Ls alias of Xd[0] now safe
    if (tid < 16) {
        float4 a = red4[0][tid], b = red4[1][tid], c = red4[2][tid], d = red4[3][tid];
        invn_s[tid * 4 + 0] = 1.f / fmaxf(sqrtf(a.x + b.x + c.x + d.x), 1e-12f);
        invn_s[tid * 4 + 1] = 1.f / fmaxf(sqrtf(a.y + b.y + c.y + d.y), 1e-12f);
        invn_s[tid * 4 + 2] = 1.f / fmaxf(sqrtf(a.z + b.z + c.z + d.z), 1e-12f);
        invn_s[tid * 4 + 3] = 1.f / fmaxf(sqrtf(a.w + b.w + c.w + d.w), 1e-12f);
    }
    __syncthreads();

    // unpack accumulators -> logits (Ls aliases Xd[0])
#pragma unroll
    for (int p = 0; p < 4; p++) {
        int r0 = k0 + 2 * p, r1 = r0 + 1;
        float b0 = bsm[r0], b1 = bsm[r1];
#pragma unroll
        for (int j = 0; j < 4; j++) {
            int cA = nl + j;
            float iA = invn_s[cA];
            float lo, hi;
            upk2(acc[p][j], lo, hi);
            Ls[r0 * 64 + cA] = lo * iA + b0;
            Ls[r1 * 64 + cA] = hi * iA + b1;
        }
    }
    __syncthreads();

    // softmax over k per column
    const int col  = tid & 63;
    const int half = tid >> 6;
    float m = -1e30f;
#pragma unroll
    for (int kk = 0; kk < 32; kk++) m = fmaxf(m, Ls[(half * 32 + kk) * 64 + col]);
    red[half * 64 + col] = m;
    __syncthreads();
    m = fmaxf(red[col], red[64 + col]);
    __syncthreads();
    float s = 0.f;
#pragma unroll
    for (int kk = 0; kk < 32; kk++) {
        float e = __expf(Ls[(half * 32 + kk) * 64 + col] - m);
        Ls[(half * 32 + kk) * 64 + col] = e;
        s += e;
    }
    red[half * 64 + col] = s;
    __syncthreads();
    const int  n     = n0 + col;
    const bool valid = (n < N_);
    float S    = red[col] + red[64 + col];
    float rinv = valid ? (1.f / S) : 0.f;
    if (half == 0) rinvs[col] = rinv;
    __syncthreads();

    // write aT' = a * invn  ([t][n][k])
    if (valid) {
        float  sc  = rinv * invn_s[col];
        float4* dst = (float4*)&g_aT[((size_t)t * N_ + n) * K_ + half * 32];
#pragma unroll
        for (int q = 0; q < 8; q++) {
            int kb = half * 32 + q * 4;
            float4 v;
            v.x = Ls[(kb + 0) * 64 + col] * sc;
            v.y = Ls[(kb + 1) * 64 + col] * sc;
            v.z = Ls[(kb + 2) * 64 + col] * sc;
            v.w = Ls[(kb + 3) * 64 + col] * sc;
            dst[q] = v;
        }
    }

    // partial asum per k -> plain store (no atomics)
    if (tid < 64) {
        float as = 0.f;
#pragma unroll 8
        for (int c2 = 0; c2 < 64; c2++) {
            int cix = (c2 + tid) & 63;
            as += Ls[tid * 64 + cix] * rinvs[cix];
        }
        g_asump[((size_t)t * NB_ + blockIdx.x) * K_ + tid] = as;
    }
}

// ---------------- pass 2: VLAD GEMM (split-2 disjoint slabs, double-buffered, LDS.64 feeds) ----------------
// grid (8, 2, T), block 128.  Tile K=64 x C=64.
__global__ __launch_bounds__(128) void vlad_kernel(const float* __restrict__ x)
{
    const int t   = blockIdx.z;
    const int c0  = blockIdx.x * 64;
    const int s   = blockIdx.y;
    const int tid = threadIdx.x;
    const int tyk = tid >> 4;
    const int txc = tid & 15;
    const int k0  = tyk * 8;
    const int cl  = txc * 4;

    __shared__ float As[2][2048];      // [buf][nn][k]
    __shared__ float Xd[2][4160];      // [buf] nn*130 + j*32 + txc*2 (+dup)

    u64 acc[4][4];
#pragma unroll
    for (int p = 0; p < 4; p++)
#pragma unroll
        for (int j = 0; j < 4; j++) acc[p][j] = 0ull;

    const float* xt  = x + (size_t)t * C_ * N_;
    const float* aTt = g_aT + (size_t)t * N_ * K_;

    const int cb = (s == 0) ? 0  : 13;
    const int NC = (s == 0) ? 13 : 12;

    // prologue: chunk cb -> buffer 0
    {
        const int n0 = cb * 32;
#pragma unroll
        for (int j = 0; j < 4; j++) {
            int e = tid + j * 128;
            int nn = e >> 4, k4 = e & 15;
            float4 v = make_float4(0.f, 0.f, 0.f, 0.f);
            if (n0 + nn < N_) v = *(const float4*)&aTt[(size_t)(n0 + nn) * K_ + k4 * 4];
            ((float4*)As[0])[e] = v;
        }
#pragma unroll
        for (int j = 0; j < 16; j++) {
            int e  = tid + j * 128;
            int ci = e >> 5, nn = e & 31;
            float v = (n0 + nn < N_) ? xt[(size_t)(c0 + ci) * N_ + n0 + nn] : 0.f;
            *(u64*)&Xd[0][nn * 130 + (ci & 3) * 32 + (ci >> 2) * 2] = pk2(v, v);
        }
    }
    __syncthreads();

    for (int i = 0; i < NC; i++) {
        const int p = i & 1;
        float4 apre[4];
        float  xpre[16];
        if (i + 1 < NC) {
            const int n0 = (cb + i + 1) * 32;
#pragma unroll
            for (int j = 0; j < 4; j++) {
                int e = tid + j * 128;
                int nn = e >> 4, k4 = e & 15;
                apre[j] = make_float4(0.f, 0.f, 0.f, 0.f);
                if (n0 + nn < N_) apre[j] = *(const float4*)&aTt[(size_t)(n0 + nn) * K_ + k4 * 4];
            }
#pragma unroll
            for (int j = 0; j < 16; j++) {
                int e  = tid + j * 128;
                int ci = e >> 5, nn = e & 31;
                xpre[j] = (n0 + nn < N_) ? xt[(size_t)(c0 + ci) * N_ + n0 + nn] : 0.f;
            }
        }

        const float* Ap = As[p];
        const float* Xp = Xd[p];
#pragma unroll
        for (int nn = 0; nn < 32; nn++) {
            u64 ap0 = *(const u64*)&Ap[nn * 64 + k0 + 0];
            u64 ap1 = *(const u64*)&Ap[nn * 64 + k0 + 2];
            u64 ap2 = *(const u64*)&Ap[nn * 64 + k0 + 4];
            u64 ap3 = *(const u64*)&Ap[nn * 64 + k0 + 6];
            u64 xd0 = *(const u64*)&Xp[nn * 130 +  0 + txc * 2];
            u64 xd1 = *(const u64*)&Xp[nn * 130 + 32 + txc * 2];
            u64 xd2 = *(const u64*)&Xp[nn * 130 + 64 + txc * 2];
            u64 xd3 = *(const u64*)&Xp[nn * 130 + 96 + txc * 2];
            fma2(acc[0][0], ap0, xd0); fma2(acc[0][1], ap0, xd1);
            fma2(acc[0][2], ap0, xd2); fma2(acc[0][3], ap0, xd3);
            fma2(acc[1][0], ap1, xd0); fma2(acc[1][1], ap1, xd1);
            fma2(acc[1][2], ap1, xd2); fma2(acc[1][3], ap1, xd3);
            fma2(acc[2][0], ap2, xd0); fma2(acc[2][1], ap2, xd1);
            fma2(acc[2][2], ap2, xd2); fma2(acc[2][3], ap2, xd3);
            fma2(acc[3][0], ap3, xd0); fma2(acc[3][1], ap3, xd1);
            fma2(acc[3][2], ap3, xd2); fma2(acc[3][3], ap3, xd3);
        }

        if (i + 1 < NC) {
            const int q = p ^ 1;
#pragma unroll
            for (int j = 0; j < 4; j++)
                ((float4*)As[q])[tid + j * 128] = apre[j];
#pragma unroll
            for (int j = 0; j < 16; j++) {
                int e  = tid + j * 128;
                int ci = e >> 5, nn = e & 31;
                *(u64*)&Xd[q][nn * 130 + (ci & 3) * 32 + (ci >> 2) * 2] = pk2(xpre[j], xpre[j]);
            }
            __syncthreads();
        }
    }

    // epilogue: float4 stores into this split's slab
    float* slab = (s == 0) ? g_vladA : g_vladB;
#pragma unroll
    for (int p = 0; p < 4; p++) {
        int r0 = k0 + 2 * p, r1 = r0 + 1;
        float lo0, hi0, lo1, hi1, lo2, hi2, lo3, hi3;
        upk2(acc[p][0], lo0, hi0);
        upk2(acc[p][1], lo1, hi1);
        upk2(acc[p][2], lo2, hi2);
        upk2(acc[p][3], lo3, hi3);
        float4 v0 = make_float4(lo0, lo1, lo2, lo3);
        float4 v1 = make_float4(hi0, hi1, hi2, hi3);
        *(float4*)&slab[((size_t)t * K_ + r0) * C_ + c0 + cl] = v0;
        *(float4*)&slab[((size_t)t * K_ + r1) * C_ + c0 + cl] = v1;
    }
}

// ---------------- pass 3: sum partials + (-asum*cent) + intra-norm ----------------
// grid T*K/4 = 480, block 128 (warp per (t,k) row)
__global__ __launch_bounds__(128) void intranorm_kernel(const float* __restrict__ cent) {
    const int warp = threadIdx.x >> 5;
    const int lane = threadIdx.x & 31;
    const int row  = blockIdx.x * 4 + warp;
    const int t = row >> 6, k = row & 63;

    float as = 0.f;
#pragma unroll
    for (int b = 0; b < NB_; b++)
        as += g_asump[((size_t)t * NB_ + b) * K_ + k];

    const size_t base4 = (size_t)row * (C_ / 4);
    const float4* A = (const float4*)g_vladA;
    const float4* B = (const float4*)g_vladB;
    const float4* CW = (const float4*)cent;

    float4 val[4];
    float ss = 0.f;
#pragma unroll
    for (int q = 0; q < 4; q++) {
        int idx = q * 32 + lane;
        float4 a = A[base4 + idx];
        float4 b = B[base4 + idx];
        float4 cw = CW[(size_t)k * (C_ / 4) + idx];
        float4 v;
        v.x = a.x + b.x - as * cw.x;
        v.y = a.y + b.y - as * cw.y;
        v.z = a.z + b.z - as * cw.z;
        v.w = a.w + b.w - as * cw.w;
        val[q] = v;
        ss += v.x * v.x + v.y * v.y + v.z * v.z + v.w * v.w;
    }
#pragma unroll
    for (int o = 16; o; o >>= 1) ss += __shfl_xor_sync(0xffffffff, ss, o);
    float sc = 1.f / fmaxf(sqrtf(ss), 1e-12f);
    float4* Aout = (float4*)g_vladA;
#pragma unroll
    for (int q = 0; q < 4; q++) {
        int idx = q * 32 + lane;
        float4 v = val[q];
        v.x *= sc; v.y *= sc; v.z *= sc; v.w *= sc;
        Aout[base4 + idx] = v;
    }
    if (lane == 0) g_gssp[row] = ss * sc * sc;
}

// ---------------- pass 4: reduce gss + global normalize + sum over t ----------------
__global__ __launch_bounds__(256) void finalize_kernel(float* __restrict__ out) {
    __shared__ float sp[T_ * K_];
    __shared__ float gsc[T_];
    const int tid = threadIdx.x;
    for (int i = tid; i < T_ * K_; i += 256) sp[i] = g_gssp[i];
    __syncthreads();
    if (tid < T_) {
        float s = 0.f;
#pragma unroll 8
        for (int q = 0; q < K_; q++) s += sp[tid * K_ + q];
        gsc[tid] = 1.f / fmaxf(sqrtf(s), 1e-12f);
    }
    __syncthreads();
    const int i = blockIdx.x * 256 + tid;
    float s = 0.f;
    for (int t = 0; t < T_; t++)
        s += g_vladA[(size_t)t * KD_ + i] * gsc[t];
    out[i] = s;
}

// ---------------- launch ----------------
extern "C" void kernel_launch(void* const* d_in, const int* in_sizes, int n_in,
                              void* d_out, int out_size) {
    const float* x1     = (const float*)d_in[0];   // [30,512,28,28]
    const float* cent   = (const float*)d_in[1];   // [64,512]
    const float* conv_w = (const float*)d_in[2];   // [64,512]
    const float* conv_b = (const float*)d_in[3];   // [64]
    float* out = (float*)d_out;                    // [1, 32768]

    {
        dim3 g(NB_, T_);
        assign_kernel<<<g, 128>>>(x1, conv_w, conv_b);
    }
    {
        dim3 g(C_ / 64, 2, T_);
        vlad_kernel<<<g, 128>>>(x1);
    }
    intranorm_kernel<<<(T_ * K_) / 4, 128>>>(cent);
    finalize_kernel<<<KD_ / 256, 256>>>(out);
}

// round 9
// speedup vs baseline: 1.3313x; 1.3313x over previous
#include <cuda_runtime.h>
#include <math.h>

#define T_ 30
#define C_ 512
#define N_ 784
#define K_ 64
#define KD_ (K_ * C_)   // 32768
#define NB_ 13          // assign n-tiles per t

// ---------------- device scratch ----------------
__device__ float g_wT[C_ * K_];             // conv_w transposed: [c][k]
__device__ float g_aT[T_ * N_ * K_];        // a' = softmax * invn, [t][n][k]
__device__ float g_asump[T_ * NB_ * K_];    // per-block partial asum
__device__ float g_vladA[T_ * K_ * C_];     // partial s0 -> normalized vlad
__device__ float g_vladB[T_ * K_ * C_];     // partial s1
__device__ float g_vladC[T_ * K_ * C_];     // partial s2
__device__ float g_gssp[T_ * K_];           // per-row sumsq (post-intra-norm)

typedef unsigned long long u64;
__device__ __forceinline__ u64 pk2(float lo, float hi) {
    u64 r;
    asm("mov.b64 %0, {%1, %2};" : "=l"(r) : "f"(lo), "f"(hi));
    return r;
}
__device__ __forceinline__ void upk2(u64 v, float& lo, float& hi) {
    asm("mov.b64 {%0, %1}, %2;" : "=f"(lo), "=f"(hi) : "l"(v));
}
__device__ __forceinline__ void fma2(u64& d, u64 a, u64 b) {
    asm("fma.rn.f32x2 %0, %1, %2, %0;" : "+l"(d) : "l"(a), "l"(b));
}

// ---------------- pass 0: transpose W ----------------
__global__ void prep_kernel(const float* __restrict__ w) {
    int i = blockIdx.x * 256 + threadIdx.x;
    if (i < C_ * K_) {
        int k = i / C_, c = i % C_;
        g_wT[c * K_ + k] = w[i];
    }
}

// ---------------- pass 1: invnorm + logits GEMM + softmax -> aT', asum partials ----------------
// grid: (13, T), block 128.  Tile: K=64 x N=64, double-buffered k-chunks.  (R6 core)
__global__ __launch_bounds__(128) void assign_kernel(
    const float* __restrict__ x, const float* __restrict__ bias)
{
    const int t   = blockIdx.y;
    const int n0  = blockIdx.x * 64;
    const int tid = threadIdx.x;
    const int tyk = tid >> 4;          // 0..7  -> k0 = tyk*8
    const int txn = tid & 15;          // 0..15 -> nl = txn*4
    const int k0  = tyk * 8;
    const int nl  = txn * 4;

    __shared__ float Ws[2][2048];      // [buf][ci][k]
    __shared__ float Xs[2][2048];      // [buf][ci][nj]
    __shared__ float Ls[64 * 64];      // logits/exp [k][n]
    __shared__ float red[2 * 64];
    __shared__ float invn_s[64];
    __shared__ float rinvs[64];
    __shared__ float bsm[64];

    if (tid < 64) bsm[tid] = bias[tid];

    u64 acc[4][4];
#pragma unroll
    for (int p = 0; p < 4; p++)
#pragma unroll
        for (int j = 0; j < 4; j++) acc[p][j] = 0ull;

    const int col  = tid & 63;
    const int half = tid >> 6;
    float ss = 0.f;

    const float* xt = x + (size_t)t * C_ * N_;

    // prologue: fill buffer 0 with chunk cc=0
#pragma unroll
    for (int j = 0; j < 4; j++) {
        int idx4 = tid + j * 128;
        ((float4*)Ws[0])[idx4] = ((const float4*)g_wT)[idx4];
        int ci = idx4 >> 4, c4 = idx4 & 15;
        int n  = n0 + c4 * 4;
        float4 v = make_float4(0.f, 0.f, 0.f, 0.f);
        if (n < N_) v = *(const float4*)&xt[(size_t)ci * N_ + n];
        ((float4*)Xs[0])[idx4] = v;
    }
    __syncthreads();

    for (int cc = 0; cc < 16; cc++) {
        const int p = cc & 1;
        float4 wpre[4], xpre[4];
        if (cc < 15) {
#pragma unroll
            for (int j = 0; j < 4; j++) {
                int idx4 = tid + j * 128;
                wpre[j] = ((const float4*)(g_wT + (cc + 1) * 2048))[idx4];
                int ci = idx4 >> 4, c4 = idx4 & 15;
                int n  = n0 + c4 * 4;
                xpre[j] = make_float4(0.f, 0.f, 0.f, 0.f);
                if (n < N_) xpre[j] = *(const float4*)&xt[(size_t)((cc + 1) * 32 + ci) * N_ + n];
            }
        }

        const float* Wp = Ws[p];
        const float* Xp = Xs[p];

        // per-column sumsq (2 threads per column, 16 ci each)
#pragma unroll
        for (int q = 0; q < 16; q++) {
            float v = Xp[(half * 16 + q) * 64 + col];
            ss += v * v;
        }

#pragma unroll
        for (int ci = 0; ci < 32; ci++) {
            float4 wa = *(const float4*)&Wp[ci * 64 + k0];
            float4 wb = *(const float4*)&Wp[ci * 64 + k0 + 4];
            float4 xv = *(const float4*)&Xp[ci * 64 + nl];
            u64 wp0 = pk2(wa.x, wa.y), wp1 = pk2(wa.z, wa.w);
            u64 wp2 = pk2(wb.x, wb.y), wp3 = pk2(wb.z, wb.w);
            u64 xd0 = pk2(xv.x, xv.x), xd1 = pk2(xv.y, xv.y);
            u64 xd2 = pk2(xv.z, xv.z), xd3 = pk2(xv.w, xv.w);
            fma2(acc[0][0], wp0, xd0); fma2(acc[0][1], wp0, xd1);
            fma2(acc[0][2], wp0, xd2); fma2(acc[0][3], wp0, xd3);
            fma2(acc[1][0], wp1, xd0); fma2(acc[1][1], wp1, xd1);
            fma2(acc[1][2], wp1, xd2); fma2(acc[1][3], wp1, xd3);
            fma2(acc[2][0], wp2, xd0); fma2(acc[2][1], wp2, xd1);
            fma2(acc[2][2], wp2, xd2); fma2(acc[2][3], wp2, xd3);
            fma2(acc[3][0], wp3, xd0); fma2(acc[3][1], wp3, xd1);
            fma2(acc[3][2], wp3, xd2); fma2(acc[3][3], wp3, xd3);
        }

        if (cc < 15) {
#pragma unroll
            for (int j = 0; j < 4; j++) {
                int idx4 = tid + j * 128;
                ((float4*)Ws[p ^ 1])[idx4] = wpre[j];
                ((float4*)Xs[p ^ 1])[idx4] = xpre[j];
            }
            __syncthreads();
        }
    }

    // reduce sumsq halves -> invn
    red[half * 64 + col] = ss;
    __syncthreads();
    if (tid < 64) {
        float sst = red[tid] + red[64 + tid];
        invn_s[tid] = 1.f / fmaxf(sqrtf(sst), 1e-12f);
    }
    __syncthreads();

    // unpack accumulators -> logits in Ls
#pragma unroll
    for (int p = 0; p < 4; p++) {
        int r0 = k0 + 2 * p, r1 = r0 + 1;
        float b0 = bsm[r0], b1 = bsm[r1];
#pragma unroll
        for (int j = 0; j < 4; j++) {
            int cA = nl + j;
            float iA = invn_s[cA];
            float lo, hi;
            upk2(acc[p][j], lo, hi);
            Ls[r0 * 64 + cA] = lo * iA + b0;
            Ls[r1 * 64 + cA] = hi * iA + b1;
        }
    }
    __syncthreads();

    // softmax over k per column: 2 threads per column, 32 rows each
    float m = -1e30f;
#pragma unroll
    for (int kk = 0; kk < 32; kk++) m = fmaxf(m, Ls[(half * 32 + kk) * 64 + col]);
    red[half * 64 + col] = m;
    __syncthreads();
    m = fmaxf(red[col], red[64 + col]);
    __syncthreads();
    float s = 0.f;
#pragma unroll
    for (int kk = 0; kk < 32; kk++) {
        float e = __expf(Ls[(half * 32 + kk) * 64 + col] - m);
        Ls[(half * 32 + kk) * 64 + col] = e;
        s += e;
    }
    red[half * 64 + col] = s;
    __syncthreads();
    const int  n     = n0 + col;
    const bool valid = (n < N_);
    float S    = red[col] + red[64 + col];
    float rinv = valid ? (1.f / S) : 0.f;
    if (half == 0) rinvs[col] = rinv;
    __syncthreads();

    // write aT' = a * invn  ([t][n][k]) — float4 stores
    if (valid) {
        float  sc  = rinv * invn_s[col];
        float4* dst = (float4*)&g_aT[((size_t)t * N_ + n) * K_ + half * 32];
#pragma unroll
        for (int q = 0; q < 8; q++) {
            int kb = half * 32 + q * 4;
            float4 v;
            v.x = Ls[(kb + 0) * 64 + col] * sc;
            v.y = Ls[(kb + 1) * 64 + col] * sc;
            v.z = Ls[(kb + 2) * 64 + col] * sc;
            v.w = Ls[(kb + 3) * 64 + col] * sc;
            dst[q] = v;
        }
    }

    // partial asum per k -> plain store (no atomics, no zero-init needed)
    if (tid < 64) {
        float as = 0.f;
#pragma unroll 8
        for (int c2 = 0; c2 < 64; c2++) {
            int cix = (c2 + tid) & 63;
            as += Ls[tid * 64 + cix] * rinvs[cix];
        }
        g_asump[((size_t)t * NB_ + blockIdx.x) * K_ + tid] = as;
    }
}

// ---------------- pass 2: VLAD GEMM (split-3 disjoint slabs, double-buffered; R6 core) ----------------
// grid: (8, 3, T), block 128.  Tile: K=64 x C=64.
__global__ __launch_bounds__(128) void vlad_kernel(const float* __restrict__ x)
{
    const int t   = blockIdx.z;
    const int c0  = blockIdx.x * 64;
    const int s   = blockIdx.y;
    const int tid = threadIdx.x;
    const int tyk = tid >> 4;
    const int txc = tid & 15;
    const int k0  = tyk * 8;
    const int cl  = txc * 4;

    __shared__ float As[2][2048];      // [buf][nn][k]
    __shared__ float XsT[2][32 * 68];  // [buf][nn][ci] padded

    u64 acc[4][4];
#pragma unroll
    for (int p = 0; p < 4; p++)
#pragma unroll
        for (int j = 0; j < 4; j++) acc[p][j] = 0ull;

    const float* xt  = x + (size_t)t * C_ * N_;
    const float* aTt = g_aT + (size_t)t * N_ * K_;

    const int cb = (s == 0) ? 0 : (s == 1 ? 9 : 17);
    const int NC = (s == 0) ? 9 : 8;   // chunks [cb, cb+NC) of 25 total

    // prologue: chunk cb -> buffer 0
    {
        const int n0 = cb * 32;
#pragma unroll
        for (int j = 0; j < 4; j++) {
            int idx4 = tid + j * 128;
            int nn = idx4 >> 4, k4 = idx4 & 15;
            float4 v = make_float4(0.f, 0.f, 0.f, 0.f);
            if (n0 + nn < N_) v = *(const float4*)&aTt[(size_t)(n0 + nn) * K_ + k4 * 4];
            ((float4*)As[0])[idx4] = v;
        }
#pragma unroll
        for (int j = 0; j < 16; j++) {
            int e  = tid + j * 128;
            int ci = e >> 5, nn = e & 31;
            float v = (n0 + nn < N_) ? xt[(size_t)(c0 + ci) * N_ + n0 + nn] : 0.f;
            XsT[0][nn * 68 + ci] = v;
        }
    }
    __syncthreads();

    for (int i = 0; i < NC; i++) {
        const int p = i & 1;
        float4 apre[4];
        float  xpre[16];
        if (i + 1 < NC) {
            const int n0 = (cb + i + 1) * 32;
#pragma unroll
            for (int j = 0; j < 4; j++) {
                int idx4 = tid + j * 128;
                int nn = idx4 >> 4, k4 = idx4 & 15;
                apre[j] = make_float4(0.f, 0.f, 0.f, 0.f);
                if (n0 + nn < N_) apre[j] = *(const float4*)&aTt[(size_t)(n0 + nn) * K_ + k4 * 4];
            }
#pragma unroll
            for (int j = 0; j < 16; j++) {
                int e  = tid + j * 128;
                int ci = e >> 5, nn = e & 31;
                xpre[j] = (n0 + nn < N_) ? xt[(size_t)(c0 + ci) * N_ + n0 + nn] : 0.f;
            }
        }

        const float* Ap = As[p];
        const float* Xp = XsT[p];
#pragma unroll
        for (int nn = 0; nn < 32; nn++) {
            float4 aa = *(const float4*)&Ap[nn * 64 + k0];
            float4 ab = *(const float4*)&Ap[nn * 64 + k0 + 4];
            float4 xv = *(const float4*)&Xp[nn * 68 + cl];
            u64 ap0 = pk2(aa.x, aa.y), ap1 = pk2(aa.z, aa.w);
            u64 ap2 = pk2(ab.x, ab.y), ap3 = pk2(ab.z, ab.w);
            u64 xd0 = pk2(xv.x, xv.x), xd1 = pk2(xv.y, xv.y);
            u64 xd2 = pk2(xv.z, xv.z), xd3 = pk2(xv.w, xv.w);
            fma2(acc[0][0], ap0, xd0); fma2(acc[0][1], ap0, xd1);
            fma2(acc[0][2], ap0, xd2); fma2(acc[0][3], ap0, xd3);
            fma2(acc[1][0], ap1, xd0); fma2(acc[1][1], ap1, xd1);
            fma2(acc[1][2], ap1, xd2); fma2(acc[1][3], ap1, xd3);
            fma2(acc[2][0], ap2, xd0); fma2(acc[2][1], ap2, xd1);
            fma2(acc[2][2], ap2, xd2); fma2(acc[2][3], ap2, xd3);
            fma2(acc[3][0], ap3, xd0); fma2(acc[3][1], ap3, xd1);
            fma2(acc[3][2], ap3, xd2); fma2(acc[3][3], ap3, xd3);
        }

        if (i + 1 < NC) {
#pragma unroll
            for (int j = 0; j < 4; j++)
                ((float4*)As[p ^ 1])[tid + j * 128] = apre[j];
#pragma unroll
            for (int j = 0; j < 16; j++) {
                int e  = tid + j * 128;
                int ci = e >> 5, nn = e & 31;
                XsT[p ^ 1][nn * 68 + ci] = xpre[j];
            }
            __syncthreads();
        }
    }

    // epilogue: plain float4 stores into this split's slab
    float* slab = (s == 0) ? g_vladA : (s == 1 ? g_vladB : g_vladC);
#pragma unroll
    for (int p = 0; p < 4; p++) {
        int r0 = k0 + 2 * p, r1 = r0 + 1;
        float lo0, hi0, lo1, hi1, lo2, hi2, lo3, hi3;
        upk2(acc[p][0], lo0, hi0);
        upk2(acc[p][1], lo1, hi1);
        upk2(acc[p][2], lo2, hi2);
        upk2(acc[p][3], lo3, hi3);
        float4 v0 = make_float4(lo0, lo1, lo2, lo3);
        float4 v1 = make_float4(hi0, hi1, hi2, hi3);
        *(float4*)&slab[((size_t)t * K_ + r0) * C_ + c0 + cl] = v0;
        *(float4*)&slab[((size_t)t * K_ + r1) * C_ + c0 + cl] = v1;
    }
}

// ---------------- pass 3: sum partials + (-asum*cent) + intra-norm (warp per row) ----------------
// grid T*K/4 = 480, block 128
__global__ __launch_bounds__(128) void intranorm_kernel(const float* __restrict__ cent) {
    const int warp = threadIdx.x >> 5;
    const int lane = threadIdx.x & 31;
    const int row  = blockIdx.x * 4 + warp;
    const int t = row >> 6, k = row & 63;

    float as = 0.f;
#pragma unroll
    for (int b = 0; b < NB_; b++)
        as += g_asump[((size_t)t * NB_ + b) * K_ + k];

    const size_t base4 = (size_t)row * (C_ / 4);
    const float4* A = (const float4*)g_vladA;
    const float4* B = (const float4*)g_vladB;
    const float4* Cc = (const float4*)g_vladC;
    const float4* CW = (const float4*)cent;

    float4 val[4];
    float ss = 0.f;
#pragma unroll
    for (int q = 0; q < 4; q++) {
        int idx = q * 32 + lane;
        float4 a = A[base4 + idx];
        float4 b = B[base4 + idx];
        float4 c = Cc[base4 + idx];
        float4 cw = CW[(size_t)k * (C_ / 4) + idx];
        float4 v;
        v.x = a.x + b.x + c.x - as * cw.x;
        v.y = a.y + b.y + c.y - as * cw.y;
        v.z = a.z + b.z + c.z - as * cw.z;
        v.w = a.w + b.w + c.w - as * cw.w;
        val[q] = v;
        ss += v.x * v.x + v.y * v.y + v.z * v.z + v.w * v.w;
    }
#pragma unroll
    for (int o = 16; o; o >>= 1) ss += __shfl_xor_sync(0xffffffff, ss, o);
    float sc = 1.f / fmaxf(sqrtf(ss), 1e-12f);
    float4* Aout = (float4*)g_vladA;
#pragma unroll
    for (int q = 0; q < 4; q++) {
        int idx = q * 32 + lane;
        float4 v = val[q];
        v.x *= sc; v.y *= sc; v.z *= sc; v.w *= sc;
        Aout[base4 + idx] = v;
    }
    if (lane == 0) g_gssp[row] = ss * sc * sc;
}

// ---------------- pass 4: reduce gss + global normalize + sum over t (unrolled) ----------------
__global__ __launch_bounds__(256) void finalize_kernel(float* __restrict__ out) {
    __shared__ float sp[T_ * K_];
    __shared__ float gsc[T_];
    const int tid = threadIdx.x;
#pragma unroll
    for (int i = tid; i < T_ * K_; i += 256) sp[i] = g_gssp[i];
    __syncthreads();
    if (tid < T_) {
        float s = 0.f;
#pragma unroll 8
        for (int q = 0; q < K_; q++) s += sp[tid * K_ + q];
        gsc[tid] = 1.f / fmaxf(sqrtf(s), 1e-12f);
    }
    __syncthreads();
    const int i = blockIdx.x * 256 + tid;
    float s = 0.f;
#pragma unroll
    for (int t = 0; t < T_; t++)
        s += g_vladA[(size_t)t * KD_ + i] * gsc[t];
    out[i] = s;
}

// ---------------- launch ----------------
extern "C" void kernel_launch(void* const* d_in, const int* in_sizes, int n_in,
                              void* d_out, int out_size) {
    const float* x1     = (const float*)d_in[0];   // [30,512,28,28]
    const float* cent   = (const float*)d_in[1];   // [64,512]
    const float* conv_w = (const float*)d_in[2];   // [64,512]
    const float* conv_b = (const float*)d_in[3];   // [64]
    float* out = (float*)d_out;                    // [1, 32768]

    prep_kernel<<<128, 256>>>(conv_w);
    {
        dim3 g(NB_, T_);
        assign_kernel<<<g, 128>>>(x1, conv_b);
    }
    {
        dim3 g(C_ / 64, 3, T_);
        vlad_kernel<<<g, 128>>>(x1);
    }
    intranorm_kernel<<<(T_ * K_) / 4, 128>>>(cent);
    finalize_kernel<<<KD_ / 256, 256>>>(out);
}

// round 11
// speedup vs baseline: 1.6365x; 1.2293x over previous
#include <cuda_runtime.h>
#include <cuda_bf16.h>
#include <math.h>
#include <stdint.h>

#define T_ 30
#define C_ 512
#define N_ 784
#define K_ 64
#define KD_ (K_ * C_)   // 32768
#define NB_ 13          // assign n-tiles per t
#define NPAD_ 832       // 13 * 64, padded n for bf16 a

// ---------------- device scratch ----------------
__device__ float g_wT[C_ * K_];                    // conv_w transposed: [c][k]
__device__ __nv_bfloat16 g_ahi[T_ * K_ * NPAD_];   // a' hi, [t][k][n]
__device__ __nv_bfloat16 g_alo[T_ * K_ * NPAD_];   // a' lo
__device__ float g_asump[T_ * NB_ * K_];           // per-block partial asum
__device__ float g_vlad[T_ * K_ * C_];             // vlad [t][k][c]
__device__ float g_gssp[T_ * K_];                  // per-row sumsq (post-intra-norm)

typedef unsigned long long u64;
__device__ __forceinline__ u64 pk2(float lo, float hi) {
    u64 r;
    asm("mov.b64 %0, {%1, %2};" : "=l"(r) : "f"(lo), "f"(hi));
    return r;
}
__device__ __forceinline__ void upk2(u64 v, float& lo, float& hi) {
    asm("mov.b64 {%0, %1}, %2;" : "=f"(lo), "=f"(hi) : "l"(v));
}
__device__ __forceinline__ void fma2(u64& d, u64 a, u64 b) {
    asm("fma.rn.f32x2 %0, %1, %2, %0;" : "+l"(d) : "l"(a), "l"(b));
}

// ---------------- mma.sync helpers (plain sm_80+ PTX, no arch-a features) ----------------
__device__ __forceinline__ void ldm_x4(uint32_t* r, uint32_t addr) {
    asm volatile("ldmatrix.sync.aligned.m8n8.x4.shared.b16 {%0,%1,%2,%3}, [%4];"
        : "=r"(r[0]), "=r"(r[1]), "=r"(r[2]), "=r"(r[3]) : "r"(addr));
}
__device__ __forceinline__ void mma_bf16(float* d, const uint32_t* a, uint32_t b0, uint32_t b1) {
    asm volatile("mma.sync.aligned.m16n8k16.row.col.f32.bf16.bf16.f32 "
        "{%0,%1,%2,%3}, {%4,%5,%6,%7}, {%8,%9}, {%0,%1,%2,%3};"
        : "+f"(d[0]), "+f"(d[1]), "+f"(d[2]), "+f"(d[3])
        : "r"(a[0]), "r"(a[1]), "r"(a[2]), "r"(a[3]), "r"(b0), "r"(b1));
}
__device__ __forceinline__ void bsplit(float v, unsigned short& h, unsigned short& l) {
    __nv_bfloat16 bh = __float2bfloat16(v);
    float rem = v - __bfloat162float(bh);
    __nv_bfloat16 bl = __float2bfloat16(rem);
    h = *reinterpret_cast<unsigned short*>(&bh);
    l = *reinterpret_cast<unsigned short*>(&bl);
}

// vlad smem layout (bytes, from dynamic smem base; row stride 144B = 72 halves)
#define VA_HI 0          // a tile hi: 64 rows * 144 = 9216
#define VA_LO 9216
#define VB_HI 18432      // x tile hi: 128 rows * 144 = 18432
#define VB_LO 36864
#define V_SMEM 55296

// ---------------- pass 0: transpose W + zero bf16-a tails ----------------
__global__ void prep_kernel(const float* __restrict__ w) {
    int i = blockIdx.x * 256 + threadIdx.x;   // 32768 threads
    if (i < C_ * K_) {
        int k = i / C_, c = i % C_;
        g_wT[c * K_ + k] = w[i];
    }
    const int tailN = NPAD_ - N_;             // 48
    const int tot = T_ * K_ * tailN;          // 92160
    for (int j = i; j < tot; j += 32768) {
        int tk = j / tailN, n = N_ + j % tailN;
        g_ahi[(size_t)tk * NPAD_ + n] = __float2bfloat16(0.f);
        g_alo[(size_t)tk * NPAD_ + n] = __float2bfloat16(0.f);
    }
}

// ---------------- pass 1: invnorm + logits GEMM + softmax -> a(bf16 hi/lo), asum partials ----------------
// grid: (13, T), block 128.  (R6/R8 proven f32x2 core)
__global__ __launch_bounds__(128) void assign_kernel(
    const float* __restrict__ x, const float* __restrict__ bias)
{
    const int t   = blockIdx.y;
    const int n0  = blockIdx.x * 64;
    const int tid = threadIdx.x;
    const int tyk = tid >> 4;
    const int txn = tid & 15;
    const int k0  = tyk * 8;
    const int nl  = txn * 4;

    __shared__ float Ws[2][2048];
    __shared__ float Xs[2][2048];
    __shared__ float Ls[64 * 64];
    __shared__ float red[2 * 64];
    __shared__ float invn_s[64];
    __shared__ float rinvs[64];
    __shared__ float bsm[64];

    if (tid < 64) bsm[tid] = bias[tid];

    u64 acc[4][4];
#pragma unroll
    for (int p = 0; p < 4; p++)
#pragma unroll
        for (int j = 0; j < 4; j++) acc[p][j] = 0ull;

    const int col  = tid & 63;
    const int half = tid >> 6;
    float ss = 0.f;

    const float* xt = x + (size_t)t * C_ * N_;

#pragma unroll
    for (int j = 0; j < 4; j++) {
        int idx4 = tid + j * 128;
        ((float4*)Ws[0])[idx4] = ((const float4*)g_wT)[idx4];
        int ci = idx4 >> 4, c4 = idx4 & 15;
        int n  = n0 + c4 * 4;
        float4 v = make_float4(0.f, 0.f, 0.f, 0.f);
        if (n < N_) v = *(const float4*)&xt[(size_t)ci * N_ + n];
        ((float4*)Xs[0])[idx4] = v;
    }
    __syncthreads();

    for (int cc = 0; cc < 16; cc++) {
        const int p = cc & 1;
        float4 wpre[4], xpre[4];
        if (cc < 15) {
#pragma unroll
            for (int j = 0; j < 4; j++) {
                int idx4 = tid + j * 128;
                wpre[j] = ((const float4*)(g_wT + (cc + 1) * 2048))[idx4];
                int ci = idx4 >> 4, c4 = idx4 & 15;
                int n  = n0 + c4 * 4;
                xpre[j] = make_float4(0.f, 0.f, 0.f, 0.f);
                if (n < N_) xpre[j] = *(const float4*)&xt[(size_t)((cc + 1) * 32 + ci) * N_ + n];
            }
        }

        const float* Wp = Ws[p];
        const float* Xp = Xs[p];
#pragma unroll
        for (int q = 0; q < 16; q++) {
            float v = Xp[(half * 16 + q) * 64 + col];
            ss += v * v;
        }
#pragma unroll
        for (int ci = 0; ci < 32; ci++) {
            float4 wa = *(const float4*)&Wp[ci * 64 + k0];
            float4 wb = *(const float4*)&Wp[ci * 64 + k0 + 4];
            float4 xv = *(const float4*)&Xp[ci * 64 + nl];
            u64 wp0 = pk2(wa.x, wa.y), wp1 = pk2(wa.z, wa.w);
            u64 wp2 = pk2(wb.x, wb.y), wp3 = pk2(wb.z, wb.w);
            u64 xd0 = pk2(xv.x, xv.x), xd1 = pk2(xv.y, xv.y);
            u64 xd2 = pk2(xv.z, xv.z), xd3 = pk2(xv.w, xv.w);
            fma2(acc[0][0], wp0, xd0); fma2(acc[0][1], wp0, xd1);
            fma2(acc[0][2], wp0, xd2); fma2(acc[0][3], wp0, xd3);
            fma2(acc[1][0], wp1, xd0); fma2(acc[1][1], wp1, xd1);
            fma2(acc[1][2], wp1, xd2); fma2(acc[1][3], wp1, xd3);
            fma2(acc[2][0], wp2, xd0); fma2(acc[2][1], wp2, xd1);
            fma2(acc[2][2], wp2, xd2); fma2(acc[2][3], wp2, xd3);
            fma2(acc[3][0], wp3, xd0); fma2(acc[3][1], wp3, xd1);
            fma2(acc[3][2], wp3, xd2); fma2(acc[3][3], wp3, xd3);
        }

        if (cc < 15) {
#pragma unroll
            for (int j = 0; j < 4; j++) {
                int idx4 = tid + j * 128;
                ((float4*)Ws[p ^ 1])[idx4] = wpre[j];
                ((float4*)Xs[p ^ 1])[idx4] = xpre[j];
            }
            __syncthreads();
        }
    }

    red[half * 64 + col] = ss;
    __syncthreads();
    if (tid < 64) {
        float sst = red[tid] + red[64 + tid];
        invn_s[tid] = 1.f / fmaxf(sqrtf(sst), 1e-12f);
    }
    __syncthreads();

#pragma unroll
    for (int p = 0; p < 4; p++) {
        int r0 = k0 + 2 * p, r1 = r0 + 1;
        float b0 = bsm[r0], b1 = bsm[r1];
#pragma unroll
        for (int j = 0; j < 4; j++) {
            int cA = nl + j;
            float iA = invn_s[cA];
            float lo, hi;
            upk2(acc[p][j], lo, hi);
            Ls[r0 * 64 + cA] = lo * iA + b0;
            Ls[r1 * 64 + cA] = hi * iA + b1;
        }
    }
    __syncthreads();

    float m = -1e30f;
#pragma unroll
    for (int kk = 0; kk < 32; kk++) m = fmaxf(m, Ls[(half * 32 + kk) * 64 + col]);
    red[half * 64 + col] = m;
    __syncthreads();
    m = fmaxf(red[col], red[64 + col]);
    __syncthreads();
    float s = 0.f;
#pragma unroll
    for (int kk = 0; kk < 32; kk++) {
        float e = __expf(Ls[(half * 32 + kk) * 64 + col] - m);
        Ls[(half * 32 + kk) * 64 + col] = e;
        s += e;
    }
    red[half * 64 + col] = s;
    __syncthreads();
    const int  n     = n0 + col;
    const bool valid = (n < N_);
    float S    = red[col] + red[64 + col];
    float rinv = valid ? (1.f / S) : 0.f;
    if (half == 0) rinvs[col] = rinv;
    __syncthreads();

    // write a' = softmax * invn as bf16 hi/lo, layout [t][k][n]
    if (valid) {
        float sc = rinv * invn_s[col];
#pragma unroll
        for (int kk = 0; kk < 32; kk++) {
            int k = half * 32 + kk;
            float v = Ls[k * 64 + col] * sc;
            unsigned short h, l;
            bsplit(v, h, l);
            size_t idx = (size_t)(t * K_ + k) * NPAD_ + n;
            *(unsigned short*)&g_ahi[idx] = h;
            *(unsigned short*)&g_alo[idx] = l;
        }
    }

    if (tid < 64) {
        float as = 0.f;
#pragma unroll 8
        for (int c2 = 0; c2 < 64; c2++) {
            int cix = (c2 + tid) & 63;
            as += Ls[tid * 64 + cix] * rinvs[cix];
        }
        g_asump[((size_t)t * NB_ + blockIdx.x) * K_ + tid] = as;
    }
}

// ---------------- pass 2: VLAD GEMM on mma.sync bf16 (split-3) ----------------
// grid (4, T), block 256 (8 warps).  D[k=64][c=128-tile] = a[64,784] @ x[128c,784]^T
// A = a tile [k][n] row-major; B = x tile [c][n] row-major (== col-major B for row.col mma).
__global__ __launch_bounds__(256) void vlad_kernel(const float* __restrict__ x)
{
    extern __shared__ char sm[];
    const int t    = blockIdx.y;
    const int c0   = blockIdx.x * 128;
    const int tid  = threadIdx.x;
    const int wid  = tid >> 5;
    const int lane = tid & 31;
    const int wm   = wid & 1;       // k base = wm*32
    const int wn   = wid >> 1;      // c base = wn*32

    uint32_t sb = (uint32_t)__cvta_generic_to_shared(sm);

    float d[8][4];
#pragma unroll
    for (int i = 0; i < 8; i++)
#pragma unroll
        for (int j = 0; j < 4; j++) d[i][j] = 0.f;

    const float* xt = x + (size_t)t * C_ * N_;
    const __nv_bfloat16* aht = g_ahi + (size_t)t * K_ * NPAD_;
    const __nv_bfloat16* alt = g_alo + (size_t)t * K_ * NPAD_;

    // ---- prologue: fill chunk 0 ----
    {
        const int n0 = 0;
#pragma unroll
        for (int it = 0; it < 4; it++) {          // x tile: 1024 tasks (r 0..127, g 0..7)
            int e = tid + it * 256;
            int r = e >> 3, g = e & 7;
            int n = n0 + g * 8;
            float4 f0 = make_float4(0.f,0.f,0.f,0.f), f1 = f0;
            if (n < N_) {
                f0 = *(const float4*)&xt[(size_t)(c0 + r) * N_ + n];
                f1 = *(const float4*)&xt[(size_t)(c0 + r) * N_ + n + 4];
            }
            float vv[8] = {f0.x,f0.y,f0.z,f0.w,f1.x,f1.y,f1.z,f1.w};
            unsigned short hh[8], ll[8];
#pragma unroll
            for (int q = 0; q < 8; q++) bsplit(vv[q], hh[q], ll[q]);
            uint4 uh, ul;
            uh.x = hh[0] | ((uint32_t)hh[1] << 16); uh.y = hh[2] | ((uint32_t)hh[3] << 16);
            uh.z = hh[4] | ((uint32_t)hh[5] << 16); uh.w = hh[6] | ((uint32_t)hh[7] << 16);
            ul.x = ll[0] | ((uint32_t)ll[1] << 16); ul.y = ll[2] | ((uint32_t)ll[3] << 16);
            ul.z = ll[4] | ((uint32_t)ll[5] << 16); ul.w = ll[6] | ((uint32_t)ll[7] << 16);
            *(uint4*)(sm + VB_HI + r * 144 + g * 16) = uh;
            *(uint4*)(sm + VB_LO + r * 144 + g * 16) = ul;
        }
#pragma unroll
        for (int it = 0; it < 2; it++) {          // a tile: 512 tasks (k 0..63, g 0..7)
            int e = tid + it * 256;
            int k = e >> 3, g = e & 7;
            size_t off = (size_t)k * NPAD_ + n0 + g * 8;
            *(uint4*)(sm + VA_HI + k * 144 + g * 16) = *(const uint4*)(aht + off);
            *(uint4*)(sm + VA_LO + k * 144 + g * 16) = *(const uint4*)(alt + off);
        }
    }
    __syncthreads();

    for (int ch = 0; ch < 13; ch++) {
        // ---- prefetch next chunk into regs ----
        float4 xp[8];
        uint4  aph[2], apl[2];
        if (ch < 12) {
            const int n0 = (ch + 1) * 64;
#pragma unroll
            for (int it = 0; it < 4; it++) {
                int e = tid + it * 256;
                int r = e >> 3, g = e & 7;
                int n = n0 + g * 8;
                xp[it*2] = make_float4(0.f,0.f,0.f,0.f);
                xp[it*2+1] = make_float4(0.f,0.f,0.f,0.f);
                if (n < N_) {
                    xp[it*2]   = *(const float4*)&xt[(size_t)(c0 + r) * N_ + n];
                    xp[it*2+1] = *(const float4*)&xt[(size_t)(c0 + r) * N_ + n + 4];
                }
            }
#pragma unroll
            for (int it = 0; it < 2; it++) {
                int e = tid + it * 256;
                int k = e >> 3, g = e & 7;
                size_t off = (size_t)k * NPAD_ + n0 + g * 8;
                aph[it] = *(const uint4*)(aht + off);
                apl[it] = *(const uint4*)(alt + off);
            }
        }

        // ---- compute: 4 ksteps of k16 ----
#pragma unroll
        for (int ks = 0; ks < 4; ks++) {
            uint32_t Ah[2][4], Al[2][4], Bh[2][4], Bl[2][4];
#pragma unroll
            for (int mt = 0; mt < 2; mt++) {
                int row = wm * 32 + mt * 16 + (lane & 15);
                uint32_t coff = (uint32_t)(ks * 16 + (lane >> 4) * 8) * 2;
                uint32_t adr = sb + VA_HI + row * 144 + coff;
                ldm_x4(Ah[mt], adr);
                ldm_x4(Al[mt], adr + (VA_LO - VA_HI));
            }
#pragma unroll
            for (int bp = 0; bp < 2; bp++) {
                int crow = wn * 32 + bp * 16 + ((lane >> 4) << 3) + (lane & 7);
                uint32_t coff = (uint32_t)(ks * 16 + ((lane >> 3) & 1) * 8) * 2;
                uint32_t adr = sb + VB_HI + crow * 144 + coff;
                ldm_x4(Bh[bp], adr);
                ldm_x4(Bl[bp], adr + (VB_LO - VB_HI));
            }
#pragma unroll
            for (int mt = 0; mt < 2; mt++) {
#pragma unroll
                for (int nt = 0; nt < 4; nt++) {
                    int bp = nt >> 1, hp = (nt & 1) * 2;
                    float* dd = d[mt * 4 + nt];
                    mma_bf16(dd, Ah[mt], Bh[bp][hp], Bh[bp][hp + 1]);   // ah*xh
                    mma_bf16(dd, Ah[mt], Bl[bp][hp], Bl[bp][hp + 1]);   // ah*xl
                    mma_bf16(dd, Al[mt], Bh[bp][hp], Bh[bp][hp + 1]);   // al*xh
                }
            }
        }

        // ---- store prefetched regs to smem ----
        if (ch < 12) {
            __syncthreads();
#pragma unroll
            for (int it = 0; it < 4; it++) {
                int e = tid + it * 256;
                int r = e >> 3, g = e & 7;
                float4 f0 = xp[it*2], f1 = xp[it*2+1];
                float vv[8] = {f0.x,f0.y,f0.z,f0.w,f1.x,f1.y,f1.z,f1.w};
                unsigned short hh[8], ll[8];
#pragma unroll
                for (int q = 0; q < 8; q++) bsplit(vv[q], hh[q], ll[q]);
                uint4 uh, ul;
                uh.x = hh[0] | ((uint32_t)hh[1] << 16); uh.y = hh[2] | ((uint32_t)hh[3] << 16);
                uh.z = hh[4] | ((uint32_t)hh[5] << 16); uh.w = hh[6] | ((uint32_t)hh[7] << 16);
                ul.x = ll[0] | ((uint32_t)ll[1] << 16); ul.y = ll[2] | ((uint32_t)ll[3] << 16);
                ul.z = ll[4] | ((uint32_t)ll[5] << 16); ul.w = ll[6] | ((uint32_t)ll[7] << 16);
                *(uint4*)(sm + VB_HI + r * 144 + g * 16) = uh;
                *(uint4*)(sm + VB_LO + r * 144 + g * 16) = ul;
            }
#pragma unroll
            for (int it = 0; it < 2; it++) {
                int e = tid + it * 256;
                int k = e >> 3, g = e & 7;
                *(uint4*)(sm + VA_HI + k * 144 + g * 16) = aph[it];
                *(uint4*)(sm + VA_LO + k * 144 + g * 16) = apl[it];
            }
            __syncthreads();
        }
    }

    // ---- epilogue: coalesced float2 stores, D frag rows = k, cols = c ----
#pragma unroll
    for (int mt = 0; mt < 2; mt++) {
#pragma unroll
        for (int nt = 0; nt < 4; nt++) {
            float* dd = d[mt * 4 + nt];
            int k = wm * 32 + mt * 16 + (lane >> 2);
            int c = c0 + wn * 32 + nt * 8 + (lane & 3) * 2;
            *(float2*)&g_vlad[(size_t)(t * K_ + k) * C_ + c]     = make_float2(dd[0], dd[1]);
            *(float2*)&g_vlad[(size_t)(t * K_ + k + 8) * C_ + c] = make_float2(dd[2], dd[3]);
        }
    }
}

// ---------------- pass 3: sum asum partials + (-asum*cent) + intra-norm ----------------
// grid T*K/4 = 480, block 128 (warp per (t,k) row)
__global__ __launch_bounds__(128) void intranorm_kernel(const float* __restrict__ cent) {
    const int warp = threadIdx.x >> 5;
    const int lane = threadIdx.x & 31;
    const int row  = blockIdx.x * 4 + warp;
    const int t = row >> 6, k = row & 63;

    float as = 0.f;
#pragma unroll
    for (int b = 0; b < NB_; b++)
        as += g_asump[((size_t)t * NB_ + b) * K_ + k];

    const size_t base4 = (size_t)row * (C_ / 4);
    const float4* A = (const float4*)g_vlad;
    const float4* CW = (const float4*)cent;

    float4 val[4];
    float ss = 0.f;
#pragma unroll
    for (int q = 0; q < 4; q++) {
        int idx = q * 32 + lane;
        float4 a = A[base4 + idx];
        float4 cw = CW[(size_t)k * (C_ / 4) + idx];
        float4 v;
        v.x = a.x - as * cw.x;
        v.y = a.y - as * cw.y;
        v.z = a.z - as * cw.z;
        v.w = a.w - as * cw.w;
        val[q] = v;
        ss += v.x * v.x + v.y * v.y + v.z * v.z + v.w * v.w;
    }
#pragma unroll
    for (int o = 16; o; o >>= 1) ss += __shfl_xor_sync(0xffffffff, ss, o);
    float sc = 1.f / fmaxf(sqrtf(ss), 1e-12f);
    float4* Aout = (float4*)g_vlad;
#pragma unroll
    for (int q = 0; q < 4; q++) {
        int idx = q * 32 + lane;
        float4 v = val[q];
        v.x *= sc; v.y *= sc; v.z *= sc; v.w *= sc;
        Aout[base4 + idx] = v;
    }
    if (lane == 0) g_gssp[row] = ss * sc * sc;
}

// ---------------- pass 4: reduce gss + global normalize + sum over t ----------------
__global__ __launch_bounds__(256) void finalize_kernel(float* __restrict__ out) {
    __shared__ float sp[T_ * K_];
    __shared__ float gsc[T_];
    const int tid = threadIdx.x;
#pragma unroll
    for (int i = tid; i < T_ * K_; i += 256) sp[i] = g_gssp[i];
    __syncthreads();
    if (tid < T_) {
        float s = 0.f;
#pragma unroll 8
        for (int q = 0; q < K_; q++) s += sp[tid * K_ + q];
        gsc[tid] = 1.f / fmaxf(sqrtf(s), 1e-12f);
    }
    __syncthreads();
    const int i = blockIdx.x * 256 + tid;
    float s = 0.f;
#pragma unroll
    for (int t = 0; t < T_; t++)
        s += g_vlad[(size_t)t * KD_ + i] * gsc[t];
    out[i] = s;
}

// ---------------- launch ----------------
extern "C" void kernel_launch(void* const* d_in, const int* in_sizes, int n_in,
                              void* d_out, int out_size) {
    const float* x1     = (const float*)d_in[0];   // [30,512,28,28]
    const float* cent   = (const float*)d_in[1];   // [64,512]
    const float* conv_w = (const float*)d_in[2];   // [64,512]
    const float* conv_b = (const float*)d_in[3];   // [64]
    float* out = (float*)d_out;                    // [1, 32768]

    cudaFuncSetAttribute(vlad_kernel, cudaFuncAttributeMaxDynamicSharedMemorySize, V_SMEM);

    prep_kernel<<<128, 256>>>(conv_w);
    {
        dim3 g(NB_, T_);
        assign_kernel<<<g, 128>>>(x1, conv_b);
    }
    {
        dim3 g(C_ / 128, T_);
        vlad_kernel<<<g, 256, V_SMEM>>>(x1);
    }
    intranorm_kernel<<<(T_ * K_) / 4, 128>>>(cent);
    finalize_kernel<<<KD_ / 256, 256>>>(out);
}

// round 12
// speedup vs baseline: 1.8158x; 1.1095x over previous
#include <cuda_runtime.h>
#include <cuda_bf16.h>
#include <math.h>
#include <stdint.h>

#define T_ 30
#define C_ 512
#define N_ 784
#define K_ 64
#define KD_ (K_ * C_)   // 32768
#define NB_ 13          // assign n-tiles per t
#define NPAD_ 832       // 13 * 64, padded n for bf16 a
#define LSS_ 66         // Ls row stride (floats)

// ---------------- device scratch ----------------
__device__ __nv_bfloat16 g_whi[K_ * C_];           // w hi, [k][c]
__device__ __nv_bfloat16 g_wlo[K_ * C_];           // w lo
__device__ __nv_bfloat16 g_ahi[T_ * K_ * NPAD_];   // a' hi, [t][k][n]
__device__ __nv_bfloat16 g_alo[T_ * K_ * NPAD_];   // a' lo
__device__ float g_asump[T_ * NB_ * K_];           // per-block partial asum
__device__ float g_vlad[T_ * K_ * C_];             // vlad [t][k][c]
__device__ float g_gssp[T_ * K_];                  // per-row sumsq

// ---------------- mma.sync helpers (plain sm_80+ PTX) ----------------
__device__ __forceinline__ void ldm_x4(uint32_t* r, uint32_t addr) {
    asm volatile("ldmatrix.sync.aligned.m8n8.x4.shared.b16 {%0,%1,%2,%3}, [%4];"
        : "=r"(r[0]), "=r"(r[1]), "=r"(r[2]), "=r"(r[3]) : "r"(addr));
}
__device__ __forceinline__ void ldm_x4t(uint32_t* r, uint32_t addr) {
    asm volatile("ldmatrix.sync.aligned.m8n8.x4.trans.shared.b16 {%0,%1,%2,%3}, [%4];"
        : "=r"(r[0]), "=r"(r[1]), "=r"(r[2]), "=r"(r[3]) : "r"(addr));
}
__device__ __forceinline__ void mma_bf16(float* d, const uint32_t* a, uint32_t b0, uint32_t b1) {
    asm volatile("mma.sync.aligned.m16n8k16.row.col.f32.bf16.bf16.f32 "
        "{%0,%1,%2,%3}, {%4,%5,%6,%7}, {%8,%9}, {%0,%1,%2,%3};"
        : "+f"(d[0]), "+f"(d[1]), "+f"(d[2]), "+f"(d[3])
        : "r"(a[0]), "r"(a[1]), "r"(a[2]), "r"(a[3]), "r"(b0), "r"(b1));
}
__device__ __forceinline__ void bsplit(float v, unsigned short& h, unsigned short& l) {
    __nv_bfloat16 bh = __float2bfloat16(v);
    float rem = v - __bfloat162float(bh);
    __nv_bfloat16 bl = __float2bfloat16(rem);
    h = *reinterpret_cast<unsigned short*>(&bh);
    l = *reinterpret_cast<unsigned short*>(&bl);
}

// ---------------- pass 0: split W to bf16 hi/lo + zero a tails ----------------
__global__ void prep_kernel(const float* __restrict__ w) {
    int i = blockIdx.x * 256 + threadIdx.x;   // 32768 threads == K_*C_
    unsigned short h, l;
    bsplit(w[i], h, l);
    *(unsigned short*)&g_whi[i] = h;
    *(unsigned short*)&g_wlo[i] = l;
    const int tailN = NPAD_ - N_;             // 48
    const int tot = T_ * K_ * tailN;          // 92160
    for (int j = i; j < tot; j += 32768) {
        int tk = j / tailN, n = N_ + j % tailN;
        g_ahi[(size_t)tk * NPAD_ + n] = __float2bfloat16(0.f);
        g_alo[(size_t)tk * NPAD_ + n] = __float2bfloat16(0.f);
    }
}

// ---------------- pass 1: assign on mma.sync (bf16 split-4) ----------------
// grid (13, T), block 128 (4 warps).  D[k=64][n=64] = w[64,512] @ x[512, n-tile]
// A = w[k][c] row-major (ldmatrix);  B = x stored [c][n], fragments via ldmatrix.trans.
#define AW_H 0
#define AW_L 9216
#define AX_H 18432
#define AX_L 27648
__global__ __launch_bounds__(128) void assign_kernel(
    const float* __restrict__ x, const float* __restrict__ bias)
{
    __shared__ __align__(16) char tb[36864];
    __shared__ float red[128];
    __shared__ float4 red4[4][16];
    __shared__ float invn_s[64], scv[64], rinvs[64], bsm[64];
    float* Ls = (float*)tb;                    // overlay after GEMM (64 x LSS_)

    const int t   = blockIdx.y;
    const int n0  = blockIdx.x * 64;
    const int tid = threadIdx.x;
    const int wid = tid >> 5;
    const int lane = tid & 31;
    const uint32_t sb = (uint32_t)__cvta_generic_to_shared(tb);

    if (tid < 64) bsm[tid] = bias[tid];

    float d[8][4];
#pragma unroll
    for (int g = 0; g < 8; g++)
#pragma unroll
        for (int j = 0; j < 4; j++) d[g][j] = 0.f;

    float4 ss4 = make_float4(0.f, 0.f, 0.f, 0.f);
    const float* xt = x + (size_t)t * C_ * N_;
    const int gn = tid & 15;
    const int nn = n0 + gn * 4;
    const bool nv = (nn < N_);

    for (int ch = 0; ch < 8; ch++) {
        __syncthreads();
        // W fill: 64k x 64c bf16 hi/lo, row stride 144B
#pragma unroll
        for (int it = 0; it < 4; it++) {
            int e = tid + it * 128;           // [0,512)
            int k = e >> 3, gc = e & 7;
            size_t src = (size_t)k * 1024 + ch * 128 + gc * 16;
            *(uint4*)(tb + AW_H + k * 144 + gc * 16) = *(const uint4*)((const char*)g_whi + src);
            *(uint4*)(tb + AW_L + k * 144 + gc * 16) = *(const uint4*)((const char*)g_wlo + src);
        }
        // X fill: 64c x 64n, stored [c][n] bf16 hi/lo (no transpose; ldmatrix.trans later)
#pragma unroll
        for (int it = 0; it < 8; it++) {
            int e = tid + it * 128;           // [0,1024)
            int c = e >> 4;                   // 0..63
            float4 v = make_float4(0.f, 0.f, 0.f, 0.f);
            if (nv) v = *(const float4*)&xt[(size_t)(ch * 64 + c) * N_ + nn];
            ss4.x += v.x * v.x; ss4.y += v.y * v.y; ss4.z += v.z * v.z; ss4.w += v.w * v.w;
            unsigned short h0,h1,h2,h3, l0,l1,l2,l3;
            bsplit(v.x, h0, l0); bsplit(v.y, h1, l1);
            bsplit(v.z, h2, l2); bsplit(v.w, h3, l3);
            uint2 uh, ul;
            uh.x = h0 | ((uint32_t)h1 << 16); uh.y = h2 | ((uint32_t)h3 << 16);
            ul.x = l0 | ((uint32_t)l1 << 16); ul.y = l2 | ((uint32_t)l3 << 16);
            *(uint2*)(tb + AX_H + c * 144 + gn * 8) = uh;
            *(uint2*)(tb + AX_L + c * 144 + gn * 8) = ul;
        }
        __syncthreads();

#pragma unroll
        for (int ks = 0; ks < 4; ks++) {
            uint32_t Ah[4], Al[4], Bh[4][4], Bl[4][4];
            {   // A frags: rows wid*16 + (lane&15), cols ks*16 + (lane>>4)*8
                uint32_t adr = sb + AW_H + (wid * 16 + (lane & 15)) * 144
                             + ((uint32_t)(ks * 16 + (lane >> 4) * 8)) * 2;
                ldm_x4(Ah, adr);
                ldm_x4(Al, adr + (AW_L - AW_H));
            }
#pragma unroll
            for (int q = 0; q < 4; q++) {     // B frags (trans): covers n8 groups 2q, 2q+1
                int c = ks * 16 + ((lane >> 3) & 1) * 8 + (lane & 7);
                int ncol = (2 * q + (lane >> 4)) * 8;
                uint32_t adr = sb + AX_H + c * 144 + (uint32_t)ncol * 2;
                ldm_x4t(Bh[q], adr);
                ldm_x4t(Bl[q], adr + (AX_L - AX_H));
            }
#pragma unroll
            for (int g = 0; g < 8; g++) {
                int bp = g >> 1, hp = (g & 1) * 2;
                mma_bf16(d[g], Ah, Bh[bp][hp], Bh[bp][hp + 1]);
                mma_bf16(d[g], Ah, Bl[bp][hp], Bl[bp][hp + 1]);
                mma_bf16(d[g], Al, Bh[bp][hp], Bh[bp][hp + 1]);
                mma_bf16(d[g], Al, Bl[bp][hp], Bl[bp][hp + 1]);
            }
        }
    }

    // ---- sumsq reduce -> invn ----
    ss4.x += __shfl_xor_sync(0xffffffff, ss4.x, 16);
    ss4.y += __shfl_xor_sync(0xffffffff, ss4.y, 16);
    ss4.z += __shfl_xor_sync(0xffffffff, ss4.z, 16);
    ss4.w += __shfl_xor_sync(0xffffffff, ss4.w, 16);
    if ((tid & 31) < 16) red4[tid >> 5][tid & 15] = ss4;
    __syncthreads();          // also: all mma/ldmatrix done -> Ls overlay safe
    if (tid < 16) {
        float4 a = red4[0][tid], b = red4[1][tid], c = red4[2][tid], dd = red4[3][tid];
        invn_s[tid * 4 + 0] = 1.f / fmaxf(sqrtf(a.x + b.x + c.x + dd.x), 1e-12f);
        invn_s[tid * 4 + 1] = 1.f / fmaxf(sqrtf(a.y + b.y + c.y + dd.y), 1e-12f);
        invn_s[tid * 4 + 2] = 1.f / fmaxf(sqrtf(a.z + b.z + c.z + dd.z), 1e-12f);
        invn_s[tid * 4 + 3] = 1.f / fmaxf(sqrtf(a.w + b.w + c.w + dd.w), 1e-12f);
    }
    __syncthreads();

    // ---- epilogue: fragments -> logits in Ls ----
    {
        int k = wid * 16 + (lane >> 2);
        float bk0 = bsm[k], bk1 = bsm[k + 8];
#pragma unroll
        for (int g = 0; g < 8; g++) {
            int n = g * 8 + (lane & 3) * 2;
            float i0 = invn_s[n], i1 = invn_s[n + 1];
            *(float2*)&Ls[k * LSS_ + n]       = make_float2(d[g][0] * i0 + bk0, d[g][1] * i1 + bk0);
            *(float2*)&Ls[(k + 8) * LSS_ + n] = make_float2(d[g][2] * i0 + bk1, d[g][3] * i1 + bk1);
        }
    }
    __syncthreads();

    // ---- softmax over k per column (2 threads/col, 32 rows each) ----
    const int col  = tid & 63;
    const int half = tid >> 6;
    float m = -1e30f;
#pragma unroll
    for (int kk = 0; kk < 32; kk++) m = fmaxf(m, Ls[(half * 32 + kk) * LSS_ + col]);
    red[half * 64 + col] = m;
    __syncthreads();
    m = fmaxf(red[col], red[64 + col]);
    __syncthreads();
    float s = 0.f;
#pragma unroll
    for (int kk = 0; kk < 32; kk++) {
        float e = __expf(Ls[(half * 32 + kk) * LSS_ + col] - m);
        Ls[(half * 32 + kk) * LSS_ + col] = e;
        s += e;
    }
    red[half * 64 + col] = s;
    __syncthreads();
    const bool valid = (n0 + col < N_);
    float S    = red[col] + red[64 + col];
    float rinv = valid ? (1.f / S) : 0.f;
    if (half == 0) {
        rinvs[col] = rinv;
        scv[col]   = rinv * invn_s[col];
    }
    __syncthreads();

    // ---- coalesced aT writeback: thread -> (k = tid>>1, half-row h = tid&1) ----
    {
        int k = tid >> 1, h = tid & 1;
        size_t base = (size_t)(t * K_ + k) * NPAD_ + n0 + h * 32;
#pragma unroll
        for (int j = 0; j < 4; j++) {
            unsigned short hh[8], ll[8];
#pragma unroll
            for (int q = 0; q < 8; q++) {
                int n = h * 32 + j * 8 + q;
                float v = Ls[k * LSS_ + n] * scv[n];
                bsplit(v, hh[q], ll[q]);
            }
            uint4 uh, ul;
            uh.x = hh[0] | ((uint32_t)hh[1] << 16); uh.y = hh[2] | ((uint32_t)hh[3] << 16);
            uh.z = hh[4] | ((uint32_t)hh[5] << 16); uh.w = hh[6] | ((uint32_t)hh[7] << 16);
            ul.x = ll[0] | ((uint32_t)ll[1] << 16); ul.y = ll[2] | ((uint32_t)ll[3] << 16);
            ul.z = ll[4] | ((uint32_t)ll[5] << 16); ul.w = ll[6] | ((uint32_t)ll[7] << 16);
            *(uint4*)&g_ahi[base + j * 8] = uh;
            *(uint4*)&g_alo[base + j * 8] = ul;
        }
    }

    // ---- partial asum per k ----
    if (tid < 64) {
        float as = 0.f;
#pragma unroll 8
        for (int c2 = 0; c2 < 64; c2++) {
            int cix = (c2 + tid) & 63;
            as += Ls[tid * LSS_ + cix] * rinvs[cix];
        }
        g_asump[((size_t)t * NB_ + blockIdx.x) * K_ + tid] = as;
    }
}

// ---------------- pass 2: VLAD GEMM on mma.sync bf16 (split-3) — R11, unchanged ----------------
#define VA_HI 0
#define VA_LO 9216
#define VB_HI 18432
#define VB_LO 36864
#define V_SMEM 55296
__global__ __launch_bounds__(256) void vlad_kernel(const float* __restrict__ x)
{
    extern __shared__ char sm[];
    const int t    = blockIdx.y;
    const int c0   = blockIdx.x * 128;
    const int tid  = threadIdx.x;
    const int wid  = tid >> 5;
    const int lane = tid & 31;
    const int wm   = wid & 1;
    const int wn   = wid >> 1;

    uint32_t sb = (uint32_t)__cvta_generic_to_shared(sm);

    float d[8][4];
#pragma unroll
    for (int i = 0; i < 8; i++)
#pragma unroll
        for (int j = 0; j < 4; j++) d[i][j] = 0.f;

    const float* xt = x + (size_t)t * C_ * N_;
    const __nv_bfloat16* aht = g_ahi + (size_t)t * K_ * NPAD_;
    const __nv_bfloat16* alt = g_alo + (size_t)t * K_ * NPAD_;

    {
        const int n0 = 0;
#pragma unroll
        for (int it = 0; it < 4; it++) {
            int e = tid + it * 256;
            int r = e >> 3, g = e & 7;
            int n = n0 + g * 8;
            float4 f0 = make_float4(0.f,0.f,0.f,0.f), f1 = f0;
            if (n < N_) {
                f0 = *(const float4*)&xt[(size_t)(c0 + r) * N_ + n];
                f1 = *(const float4*)&xt[(size_t)(c0 + r) * N_ + n + 4];
            }
            float vv[8] = {f0.x,f0.y,f0.z,f0.w,f1.x,f1.y,f1.z,f1.w};
            unsigned short hh[8], ll[8];
#pragma unroll
            for (int q = 0; q < 8; q++) bsplit(vv[q], hh[q], ll[q]);
            uint4 uh, ul;
            uh.x = hh[0] | ((uint32_t)hh[1] << 16); uh.y = hh[2] | ((uint32_t)hh[3] << 16);
            uh.z = hh[4] | ((uint32_t)hh[5] << 16); uh.w = hh[6] | ((uint32_t)hh[7] << 16);
            ul.x = ll[0] | ((uint32_t)ll[1] << 16); ul.y = ll[2] | ((uint32_t)ll[3] << 16);
            ul.z = ll[4] | ((uint32_t)ll[5] << 16); ul.w = ll[6] | ((uint32_t)ll[7] << 16);
            *(uint4*)(sm + VB_HI + r * 144 + g * 16) = uh;
            *(uint4*)(sm + VB_LO + r * 144 + g * 16) = ul;
        }
#pragma unroll
        for (int it = 0; it < 2; it++) {
            int e = tid + it * 256;
            int k = e >> 3, g = e & 7;
            size_t off = (size_t)k * NPAD_ + n0 + g * 8;
            *(uint4*)(sm + VA_HI + k * 144 + g * 16) = *(const uint4*)(aht + off);
            *(uint4*)(sm + VA_LO + k * 144 + g * 16) = *(const uint4*)(alt + off);
        }
    }
    __syncthreads();

    for (int ch = 0; ch < 13; ch++) {
        float4 xp[8];
        uint4  aph[2], apl[2];
        if (ch < 12) {
            const int n0 = (ch + 1) * 64;
#pragma unroll
            for (int it = 0; it < 4; it++) {
                int e = tid + it * 256;
                int r = e >> 3, g = e & 7;
                int n = n0 + g * 8;
                xp[it*2] = make_float4(0.f,0.f,0.f,0.f);
                xp[it*2+1] = make_float4(0.f,0.f,0.f,0.f);
                if (n < N_) {
                    xp[it*2]   = *(const float4*)&xt[(size_t)(c0 + r) * N_ + n];
                    xp[it*2+1] = *(const float4*)&xt[(size_t)(c0 + r) * N_ + n + 4];
                }
            }
#pragma unroll
            for (int it = 0; it < 2; it++) {
                int e = tid + it * 256;
                int k = e >> 3, g = e & 7;
                size_t off = (size_t)k * NPAD_ + n0 + g * 8;
                aph[it] = *(const uint4*)(aht + off);
                apl[it] = *(const uint4*)(alt + off);
            }
        }

#pragma unroll
        for (int ks = 0; ks < 4; ks++) {
            uint32_t Ah[2][4], Al[2][4], Bh[2][4], Bl[2][4];
#pragma unroll
            for (int mt = 0; mt < 2; mt++) {
                int row = wm * 32 + mt * 16 + (lane & 15);
                uint32_t coff = (uint32_t)(ks * 16 + (lane >> 4) * 8) * 2;
                uint32_t adr = sb + VA_HI + row * 144 + coff;
                ldm_x4(Ah[mt], adr);
                ldm_x4(Al[mt], adr + (VA_LO - VA_HI));
            }
#pragma unroll
            for (int bp = 0; bp < 2; bp++) {
                int crow = wn * 32 + bp * 16 + ((lane >> 4) << 3) + (lane & 7);
                uint32_t coff = (uint32_t)(ks * 16 + ((lane >> 3) & 1) * 8) * 2;
                uint32_t adr = sb + VB_HI + crow * 144 + coff;
                ldm_x4(Bh[bp], adr);
                ldm_x4(Bl[bp], adr + (VB_LO - VB_HI));
            }
#pragma unroll
            for (int mt = 0; mt < 2; mt++) {
#pragma unroll
                for (int nt = 0; nt < 4; nt++) {
                    int bp = nt >> 1, hp = (nt & 1) * 2;
                    float* dd = d[mt * 4 + nt];
                    mma_bf16(dd, Ah[mt], Bh[bp][hp], Bh[bp][hp + 1]);
                    mma_bf16(dd, Ah[mt], Bl[bp][hp], Bl[bp][hp + 1]);
                    mma_bf16(dd, Al[mt], Bh[bp][hp], Bh[bp][hp + 1]);
                }
            }
        }

        if (ch < 12) {
            __syncthreads();
#pragma unroll
            for (int it = 0; it < 4; it++) {
                int e = tid + it * 256;
                int r = e >> 3, g = e & 7;
                float4 f0 = xp[it*2], f1 = xp[it*2+1];
                float vv[8] = {f0.x,f0.y,f0.z,f0.w,f1.x,f1.y,f1.z,f1.w};
                unsigned short hh[8], ll[8];
#pragma unroll
                for (int q = 0; q < 8; q++) bsplit(vv[q], hh[q], ll[q]);
                uint4 uh, ul;
                uh.x = hh[0] | ((uint32_t)hh[1] << 16); uh.y = hh[2] | ((uint32_t)hh[3] << 16);
                uh.z = hh[4] | ((uint32_t)hh[5] << 16); uh.w = hh[6] | ((uint32_t)hh[7] << 16);
                ul.x = ll[0] | ((uint32_t)ll[1] << 16); ul.y = ll[2] | ((uint32_t)ll[3] << 16);
                ul.z = ll[4] | ((uint32_t)ll[5] << 16); ul.w = ll[6] | ((uint32_t)ll[7] << 16);
                *(uint4*)(sm + VB_HI + r * 144 + g * 16) = uh;
                *(uint4*)(sm + VB_LO + r * 144 + g * 16) = ul;
            }
#pragma unroll
            for (int it = 0; it < 2; it++) {
                int e = tid + it * 256;
                int k = e >> 3, g = e & 7;
                *(uint4*)(sm + VA_HI + k * 144 + g * 16) = aph[it];
                *(uint4*)(sm + VA_LO + k * 144 + g * 16) = apl[it];
            }
            __syncthreads();
        }
    }

#pragma unroll
    for (int mt = 0; mt < 2; mt++) {
#pragma unroll
        for (int nt = 0; nt < 4; nt++) {
            float* dd = d[mt * 4 + nt];
            int k = wm * 32 + mt * 16 + (lane >> 2);
            int c = c0 + wn * 32 + nt * 8 + (lane & 3) * 2;
            *(float2*)&g_vlad[(size_t)(t * K_ + k) * C_ + c]     = make_float2(dd[0], dd[1]);
            *(float2*)&g_vlad[(size_t)(t * K_ + k + 8) * C_ + c] = make_float2(dd[2], dd[3]);
        }
    }
}

// ---------------- pass 3: asum partials + (-asum*cent) + intra-norm ----------------
__global__ __launch_bounds__(128) void intranorm_kernel(const float* __restrict__ cent) {
    const int warp = threadIdx.x >> 5;
    const int lane = threadIdx.x & 31;
    const int row  = blockIdx.x * 4 + warp;
    const int t = row >> 6, k = row & 63;

    float as = 0.f;
#pragma unroll
    for (int b = 0; b < NB_; b++)
        as += g_asump[((size_t)t * NB_ + b) * K_ + k];

    const size_t base4 = (size_t)row * (C_ / 4);
    const float4* A = (const float4*)g_vlad;
    const float4* CW = (const float4*)cent;

    float4 val[4];
    float ss = 0.f;
#pragma unroll
    for (int q = 0; q < 4; q++) {
        int idx = q * 32 + lane;
        float4 a = A[base4 + idx];
        float4 cw = CW[(size_t)k * (C_ / 4) + idx];
        float4 v;
        v.x = a.x - as * cw.x;
        v.y = a.y - as * cw.y;
        v.z = a.z - as * cw.z;
        v.w = a.w - as * cw.w;
        val[q] = v;
        ss += v.x * v.x + v.y * v.y + v.z * v.z + v.w * v.w;
    }
#pragma unroll
    for (int o = 16; o; o >>= 1) ss += __shfl_xor_sync(0xffffffff, ss, o);
    float sc = 1.f / fmaxf(sqrtf(ss), 1e-12f);
    float4* Aout = (float4*)g_vlad;
#pragma unroll
    for (int q = 0; q < 4; q++) {
        int idx = q * 32 + lane;
        float4 v = val[q];
        v.x *= sc; v.y *= sc; v.z *= sc; v.w *= sc;
        Aout[base4 + idx] = v;
    }
    if (lane == 0) g_gssp[row] = ss * sc * sc;
}

// ---------------- pass 4: reduce gss + global normalize + sum over t ----------------
__global__ __launch_bounds__(256) void finalize_kernel(float* __restrict__ out) {
    __shared__ float sp[T_ * K_];
    __shared__ float gsc[T_];
    const int tid = threadIdx.x;
#pragma unroll
    for (int i = tid; i < T_ * K_; i += 256) sp[i] = g_gssp[i];
    __syncthreads();
    if (tid < T_) {
        float s = 0.f;
#pragma unroll 8
        for (int q = 0; q < K_; q++) s += sp[tid * K_ + q];
        gsc[tid] = 1.f / fmaxf(sqrtf(s), 1e-12f);
    }
    __syncthreads();
    const int i = blockIdx.x * 256 + tid;
    float s = 0.f;
#pragma unroll
    for (int t = 0; t < T_; t++)
        s += g_vlad[(size_t)t * KD_ + i] * gsc[t];
    out[i] = s;
}

// ---------------- launch ----------------
extern "C" void kernel_launch(void* const* d_in, const int* in_sizes, int n_in,
                              void* d_out, int out_size) {
    const float* x1     = (const float*)d_in[0];   // [30,512,28,28]
    const float* cent   = (const float*)d_in[1];   // [64,512]
    const float* conv_w = (const float*)d_in[2];   // [64,512]
    const float* conv_b = (const float*)d_in[3];   // [64]
    float* out = (float*)d_out;                    // [1, 32768]

    cudaFuncSetAttribute(vlad_kernel, cudaFuncAttributeMaxDynamicSharedMemorySize, V_SMEM);

    prep_kernel<<<128, 256>>>(conv_w);
    {
        dim3 g(NB_, T_);
        assign_kernel<<<g, 128>>>(x1, conv_b);
    }
    {
        dim3 g(C_ / 128, T_);
        vlad_kernel<<<g, 256, V_SMEM>>>(x1);
    }
    intranorm_kernel<<<(T_ * K_) / 4, 128>>>(cent);
    finalize_kernel<<<KD_ / 256, 256>>>(out);
}

// round 13
// speedup vs baseline: 1.8763x; 1.0333x over previous
#include <cuda_runtime.h>
#include <cuda_bf16.h>
#include <math.h>
#include <stdint.h>

#define T_ 30
#define C_ 512
#define N_ 784
#define K_ 64
#define KD_ (K_ * C_)   // 32768
#define NB_ 13          // assign n-tiles per t
#define NPAD_ 832       // 13 * 64, padded n for bf16 a
#define LSS_ 66         // Ls row stride (floats)

// ---------------- device scratch ----------------
__device__ __nv_bfloat16 g_whi[K_ * C_];           // w hi, [k][c]
__device__ __nv_bfloat16 g_wlo[K_ * C_];           // w lo
__device__ __nv_bfloat16 g_ahi[T_ * K_ * NPAD_];   // a' hi, [t][k][n]
__device__ __nv_bfloat16 g_alo[T_ * K_ * NPAD_];   // a' lo
__device__ float g_asump[T_ * NB_ * K_];           // per-block partial asum
__device__ float g_vlad[T_ * K_ * C_];             // RAW vlad [t][k][c] (never normalized in place)
__device__ float g_scv[T_ * K_];                   // per-row intra-norm scale
__device__ float g_asv[T_ * K_];                   // per-row asum
__device__ float g_ssn[T_ * K_];                   // per-row normalized sumsq (≈1)

// ---------------- mma.sync helpers (plain sm_80+ PTX) ----------------
__device__ __forceinline__ void ldm_x4(uint32_t* r, uint32_t addr) {
    asm volatile("ldmatrix.sync.aligned.m8n8.x4.shared.b16 {%0,%1,%2,%3}, [%4];"
        : "=r"(r[0]), "=r"(r[1]), "=r"(r[2]), "=r"(r[3]) : "r"(addr));
}
__device__ __forceinline__ void ldm_x4t(uint32_t* r, uint32_t addr) {
    asm volatile("ldmatrix.sync.aligned.m8n8.x4.trans.shared.b16 {%0,%1,%2,%3}, [%4];"
        : "=r"(r[0]), "=r"(r[1]), "=r"(r[2]), "=r"(r[3]) : "r"(addr));
}
__device__ __forceinline__ void mma_bf16(float* d, const uint32_t* a, uint32_t b0, uint32_t b1) {
    asm volatile("mma.sync.aligned.m16n8k16.row.col.f32.bf16.bf16.f32 "
        "{%0,%1,%2,%3}, {%4,%5,%6,%7}, {%8,%9}, {%0,%1,%2,%3};"
        : "+f"(d[0]), "+f"(d[1]), "+f"(d[2]), "+f"(d[3])
        : "r"(a[0]), "r"(a[1]), "r"(a[2]), "r"(a[3]), "r"(b0), "r"(b1));
}
__device__ __forceinline__ void bsplit(float v, unsigned short& h, unsigned short& l) {
    __nv_bfloat16 bh = __float2bfloat16(v);
    float rem = v - __bfloat162float(bh);
    __nv_bfloat16 bl = __float2bfloat16(rem);
    h = *reinterpret_cast<unsigned short*>(&bh);
    l = *reinterpret_cast<unsigned short*>(&bl);
}

// ---------------- pass 0: split W to bf16 hi/lo + zero a tails ----------------
__global__ void prep_kernel(const float* __restrict__ w) {
    int i = blockIdx.x * 256 + threadIdx.x;   // 32768 threads == K_*C_
    unsigned short h, l;
    bsplit(w[i], h, l);
    *(unsigned short*)&g_whi[i] = h;
    *(unsigned short*)&g_wlo[i] = l;
    const int tailN = NPAD_ - N_;             // 48
    const int tot = T_ * K_ * tailN;          // 92160
    for (int j = i; j < tot; j += 32768) {
        int tk = j / tailN, n = N_ + j % tailN;
        g_ahi[(size_t)tk * NPAD_ + n] = __float2bfloat16(0.f);
        g_alo[(size_t)tk * NPAD_ + n] = __float2bfloat16(0.f);
    }
}

// ---------------- pass 1: assign on mma.sync (bf16 split-4), double-buffered ----------------
// grid (13, T), block 128 (4 warps).  D[k=64][n=64] = w[64,512] @ x[512, n-tile]
#define AW_H 0
#define AW_L 9216
#define AX_H 18432
#define AX_L 27648
#define ABUF 36864
#define A_SMEM (2 * ABUF)   // 73728
__global__ __launch_bounds__(128) void assign_kernel(
    const float* __restrict__ x, const float* __restrict__ bias)
{
    extern __shared__ __align__(16) char sbuf[];
    __shared__ float red[128];
    __shared__ float4 red4[4][16];
    __shared__ float invn_s[64], scv[64], rinvs[64], bsm[64];
    float* Ls = (float*)sbuf;                  // overlay on buffer 0 after GEMM

    const int t   = blockIdx.y;
    const int n0  = blockIdx.x * 64;
    const int tid = threadIdx.x;
    const int wid = tid >> 5;
    const int lane = tid & 31;
    const uint32_t sb = (uint32_t)__cvta_generic_to_shared(sbuf);

    if (tid < 64) bsm[tid] = bias[tid];

    float d[8][4];
#pragma unroll
    for (int g = 0; g < 8; g++)
#pragma unroll
        for (int j = 0; j < 4; j++) d[g][j] = 0.f;

    float4 ss4 = make_float4(0.f, 0.f, 0.f, 0.f);
    const float* xt = x + (size_t)t * C_ * N_;
    const int gn = tid & 15;
    const int nn = n0 + gn * 4;
    const bool nv = (nn < N_);

    uint4 wh[4], wl[4];
    float4 xr[8];

    // ---- prefetch chunk 0 ----
#pragma unroll
    for (int it = 0; it < 4; it++) {
        int e = tid + it * 128;
        int k = e >> 3, gc = e & 7;
        size_t src = (size_t)k * 1024 + gc * 16;
        wh[it] = *(const uint4*)((const char*)g_whi + src);
        wl[it] = *(const uint4*)((const char*)g_wlo + src);
    }
#pragma unroll
    for (int it = 0; it < 8; it++) {
        int e = tid + it * 128;
        int c = e >> 4;
        float4 v = make_float4(0.f, 0.f, 0.f, 0.f);
        if (nv) v = *(const float4*)&xt[(size_t)c * N_ + nn];
        ss4.x += v.x * v.x; ss4.y += v.y * v.y; ss4.z += v.z * v.z; ss4.w += v.w * v.w;
        xr[it] = v;
    }
    // ---- store chunk 0 -> buffer 0 ----
#pragma unroll
    for (int it = 0; it < 4; it++) {
        int e = tid + it * 128;
        int k = e >> 3, gc = e & 7;
        *(uint4*)(sbuf + AW_H + k * 144 + gc * 16) = wh[it];
        *(uint4*)(sbuf + AW_L + k * 144 + gc * 16) = wl[it];
    }
#pragma unroll
    for (int it = 0; it < 8; it++) {
        int e = tid + it * 128;
        int c = e >> 4;
        unsigned short h0,h1,h2,h3, l0,l1,l2,l3;
        bsplit(xr[it].x, h0, l0); bsplit(xr[it].y, h1, l1);
        bsplit(xr[it].z, h2, l2); bsplit(xr[it].w, h3, l3);
        uint2 uh, ul;
        uh.x = h0 | ((uint32_t)h1 << 16); uh.y = h2 | ((uint32_t)h3 << 16);
        ul.x = l0 | ((uint32_t)l1 << 16); ul.y = l2 | ((uint32_t)l3 << 16);
        *(uint2*)(sbuf + AX_H + c * 144 + gn * 8) = uh;
        *(uint2*)(sbuf + AX_L + c * 144 + gn * 8) = ul;
    }
    __syncthreads();

    for (int ch = 0; ch < 8; ch++) {
        const int b = ch & 1;
        const uint32_t bo = (uint32_t)b * ABUF;

        // ---- prefetch chunk ch+1 into regs ----
        if (ch < 7) {
            const int chp = ch + 1;
#pragma unroll
            for (int it = 0; it < 4; it++) {
                int e = tid + it * 128;
                int k = e >> 3, gc = e & 7;
                size_t src = (size_t)k * 1024 + (size_t)chp * 128 + gc * 16;
                wh[it] = *(const uint4*)((const char*)g_whi + src);
                wl[it] = *(const uint4*)((const char*)g_wlo + src);
            }
#pragma unroll
            for (int it = 0; it < 8; it++) {
                int e = tid + it * 128;
                int c = e >> 4;
                float4 v = make_float4(0.f, 0.f, 0.f, 0.f);
                if (nv) v = *(const float4*)&xt[(size_t)(chp * 64 + c) * N_ + nn];
                ss4.x += v.x * v.x; ss4.y += v.y * v.y; ss4.z += v.z * v.z; ss4.w += v.w * v.w;
                xr[it] = v;
            }
        }

        // ---- mma on buffer b ----
#pragma unroll
        for (int ks = 0; ks < 4; ks++) {
            uint32_t Ah[4], Al[4], Bh[4][4], Bl[4][4];
            {
                uint32_t adr = sb + bo + AW_H + (wid * 16 + (lane & 15)) * 144
                             + ((uint32_t)(ks * 16 + (lane >> 4) * 8)) * 2;
                ldm_x4(Ah, adr);
                ldm_x4(Al, adr + (AW_L - AW_H));
            }
#pragma unroll
            for (int q = 0; q < 4; q++) {
                int c = ks * 16 + ((lane >> 3) & 1) * 8 + (lane & 7);
                int ncol = (2 * q + (lane >> 4)) * 8;
                uint32_t adr = sb + bo + AX_H + c * 144 + (uint32_t)ncol * 2;
                ldm_x4t(Bh[q], adr);
                ldm_x4t(Bl[q], adr + (AX_L - AX_H));
            }
#pragma unroll
            for (int g = 0; g < 8; g++) {
                int bp = g >> 1, hp = (g & 1) * 2;
                mma_bf16(d[g], Ah, Bh[bp][hp], Bh[bp][hp + 1]);
                mma_bf16(d[g], Ah, Bl[bp][hp], Bl[bp][hp + 1]);
                mma_bf16(d[g], Al, Bh[bp][hp], Bh[bp][hp + 1]);
                mma_bf16(d[g], Al, Bl[bp][hp], Bl[bp][hp + 1]);
            }
        }

        // ---- store prefetched chunk to other buffer ----
        if (ch < 7) {
            char* ob = sbuf + (b ^ 1) * ABUF;
#pragma unroll
            for (int it = 0; it < 4; it++) {
                int e = tid + it * 128;
                int k = e >> 3, gc = e & 7;
                *(uint4*)(ob + AW_H + k * 144 + gc * 16) = wh[it];
                *(uint4*)(ob + AW_L + k * 144 + gc * 16) = wl[it];
            }
#pragma unroll
            for (int it = 0; it < 8; it++) {
                int e = tid + it * 128;
                int c = e >> 4;
                unsigned short h0,h1,h2,h3, l0,l1,l2,l3;
                bsplit(xr[it].x, h0, l0); bsplit(xr[it].y, h1, l1);
                bsplit(xr[it].z, h2, l2); bsplit(xr[it].w, h3, l3);
                uint2 uh, ul;
                uh.x = h0 | ((uint32_t)h1 << 16); uh.y = h2 | ((uint32_t)h3 << 16);
                ul.x = l0 | ((uint32_t)l1 << 16); ul.y = l2 | ((uint32_t)l3 << 16);
                *(uint2*)(ob + AX_H + c * 144 + gn * 8) = uh;
                *(uint2*)(ob + AX_L + c * 144 + gn * 8) = ul;
            }
            __syncthreads();
        }
    }

    // ---- sumsq reduce -> invn ----
    ss4.x += __shfl_xor_sync(0xffffffff, ss4.x, 16);
    ss4.y += __shfl_xor_sync(0xffffffff, ss4.y, 16);
    ss4.z += __shfl_xor_sync(0xffffffff, ss4.z, 16);
    ss4.w += __shfl_xor_sync(0xffffffff, ss4.w, 16);
    if ((tid & 31) < 16) red4[tid >> 5][tid & 15] = ss4;
    __syncthreads();          // all GEMM reads done -> Ls overlay (buffer 0) safe
    if (tid < 16) {
        float4 a = red4[0][tid], b = red4[1][tid], c = red4[2][tid], dd = red4[3][tid];
        invn_s[tid * 4 + 0] = 1.f / fmaxf(sqrtf(a.x + b.x + c.x + dd.x), 1e-12f);
        invn_s[tid * 4 + 1] = 1.f / fmaxf(sqrtf(a.y + b.y + c.y + dd.y), 1e-12f);
        invn_s[tid * 4 + 2] = 1.f / fmaxf(sqrtf(a.z + b.z + c.z + dd.z), 1e-12f);
        invn_s[tid * 4 + 3] = 1.f / fmaxf(sqrtf(a.w + b.w + c.w + dd.w), 1e-12f);
    }
    __syncthreads();

    // ---- epilogue: fragments -> logits in Ls ----
    {
        int k = wid * 16 + (lane >> 2);
        float bk0 = bsm[k], bk1 = bsm[k + 8];
#pragma unroll
        for (int g = 0; g < 8; g++) {
            int n = g * 8 + (lane & 3) * 2;
            float i0 = invn_s[n], i1 = invn_s[n + 1];
            *(float2*)&Ls[k * LSS_ + n]       = make_float2(d[g][0] * i0 + bk0, d[g][1] * i1 + bk0);
            *(float2*)&Ls[(k + 8) * LSS_ + n] = make_float2(d[g][2] * i0 + bk1, d[g][3] * i1 + bk1);
        }
    }
    __syncthreads();

    // ---- softmax over k per column ----
    const int col  = tid & 63;
    const int half = tid >> 6;
    float m = -1e30f;
#pragma unroll
    for (int kk = 0; kk < 32; kk++) m = fmaxf(m, Ls[(half * 32 + kk) * LSS_ + col]);
    red[half * 64 + col] = m;
    __syncthreads();
    m = fmaxf(red[col], red[64 + col]);
    __syncthreads();
    float s = 0.f;
#pragma unroll
    for (int kk = 0; kk < 32; kk++) {
        float e = __expf(Ls[(half * 32 + kk) * LSS_ + col] - m);
        Ls[(half * 32 + kk) * LSS_ + col] = e;
        s += e;
    }
    red[half * 64 + col] = s;
    __syncthreads();
    const bool valid = (n0 + col < N_);
    float S    = red[col] + red[64 + col];
    float rinv = valid ? (1.f / S) : 0.f;
    if (half == 0) {
        rinvs[col] = rinv;
        scv[col]   = rinv * invn_s[col];
    }
    __syncthreads();

    // ---- coalesced aT writeback ----
    {
        int k = tid >> 1, h = tid & 1;
        size_t base = (size_t)(t * K_ + k) * NPAD_ + n0 + h * 32;
#pragma unroll
        for (int j = 0; j < 4; j++) {
            unsigned short hh[8], ll[8];
#pragma unroll
            for (int q = 0; q < 8; q++) {
                int n = h * 32 + j * 8 + q;
                float v = Ls[k * LSS_ + n] * scv[n];
                bsplit(v, hh[q], ll[q]);
            }
            uint4 uh, ul;
            uh.x = hh[0] | ((uint32_t)hh[1] << 16); uh.y = hh[2] | ((uint32_t)hh[3] << 16);
            uh.z = hh[4] | ((uint32_t)hh[5] << 16); uh.w = hh[6] | ((uint32_t)hh[7] << 16);
            ul.x = ll[0] | ((uint32_t)ll[1] << 16); ul.y = ll[2] | ((uint32_t)ll[3] << 16);
            ul.z = ll[4] | ((uint32_t)ll[5] << 16); ul.w = ll[6] | ((uint32_t)ll[7] << 16);
            *(uint4*)&g_ahi[base + j * 8] = uh;
            *(uint4*)&g_alo[base + j * 8] = ul;
        }
    }

    // ---- partial asum per k ----
    if (tid < 64) {
        float as = 0.f;
#pragma unroll 8
        for (int c2 = 0; c2 < 64; c2++) {
            int cix = (c2 + tid) & 63;
            as += Ls[tid * LSS_ + cix] * rinvs[cix];
        }
        g_asump[((size_t)t * NB_ + blockIdx.x) * K_ + tid] = as;
    }
}

// ---------------- pass 2: VLAD GEMM on mma.sync bf16 (split-3) — unchanged R11/R12 core ----------------
#define VA_HI 0
#define VA_LO 9216
#define VB_HI 18432
#define VB_LO 36864
#define V_SMEM 55296
__global__ __launch_bounds__(256) void vlad_kernel(const float* __restrict__ x)
{
    extern __shared__ char sm[];
    const int t    = blockIdx.y;
    const int c0   = blockIdx.x * 128;
    const int tid  = threadIdx.x;
    const int wid  = tid >> 5;
    const int lane = tid & 31;
    const int wm   = wid & 1;
    const int wn   = wid >> 1;

    uint32_t sb = (uint32_t)__cvta_generic_to_shared(sm);

    float d[8][4];
#pragma unroll
    for (int i = 0; i < 8; i++)
#pragma unroll
        for (int j = 0; j < 4; j++) d[i][j] = 0.f;

    const float* xt = x + (size_t)t * C_ * N_;
    const __nv_bfloat16* aht = g_ahi + (size_t)t * K_ * NPAD_;
    const __nv_bfloat16* alt = g_alo + (size_t)t * K_ * NPAD_;

    {
        const int n0 = 0;
#pragma unroll
        for (int it = 0; it < 4; it++) {
            int e = tid + it * 256;
            int r = e >> 3, g = e & 7;
            int n = n0 + g * 8;
            float4 f0 = make_float4(0.f,0.f,0.f,0.f), f1 = f0;
            if (n < N_) {
                f0 = *(const float4*)&xt[(size_t)(c0 + r) * N_ + n];
                f1 = *(const float4*)&xt[(size_t)(c0 + r) * N_ + n + 4];
            }
            float vv[8] = {f0.x,f0.y,f0.z,f0.w,f1.x,f1.y,f1.z,f1.w};
            unsigned short hh[8], ll[8];
#pragma unroll
            for (int q = 0; q < 8; q++) bsplit(vv[q], hh[q], ll[q]);
            uint4 uh, ul;
            uh.x = hh[0] | ((uint32_t)hh[1] << 16); uh.y = hh[2] | ((uint32_t)hh[3] << 16);
            uh.z = hh[4] | ((uint32_t)hh[5] << 16); uh.w = hh[6] | ((uint32_t)hh[7] << 16);
            ul.x = ll[0] | ((uint32_t)ll[1] << 16); ul.y = ll[2] | ((uint32_t)ll[3] << 16);
            ul.z = ll[4] | ((uint32_t)ll[5] << 16); ul.w = ll[6] | ((uint32_t)ll[7] << 16);
            *(uint4*)(sm + VB_HI + r * 144 + g * 16) = uh;
            *(uint4*)(sm + VB_LO + r * 144 + g * 16) = ul;
        }
#pragma unroll
        for (int it = 0; it < 2; it++) {
            int e = tid + it * 256;
            int k = e >> 3, g = e & 7;
            size_t off = (size_t)k * NPAD_ + n0 + g * 8;
            *(uint4*)(sm + VA_HI + k * 144 + g * 16) = *(const uint4*)(aht + off);
            *(uint4*)(sm + VA_LO + k * 144 + g * 16) = *(const uint4*)(alt + off);
        }
    }
    __syncthreads();

    for (int ch = 0; ch < 13; ch++) {
        float4 xp[8];
        uint4  aph[2], apl[2];
        if (ch < 12) {
            const int n0 = (ch + 1) * 64;
#pragma unroll
            for (int it = 0; it < 4; it++) {
                int e = tid + it * 256;
                int r = e >> 3, g = e & 7;
                int n = n0 + g * 8;
                xp[it*2] = make_float4(0.f,0.f,0.f,0.f);
                xp[it*2+1] = make_float4(0.f,0.f,0.f,0.f);
                if (n < N_) {
                    xp[it*2]   = *(const float4*)&xt[(size_t)(c0 + r) * N_ + n];
                    xp[it*2+1] = *(const float4*)&xt[(size_t)(c0 + r) * N_ + n + 4];
                }
            }
#pragma unroll
            for (int it = 0; it < 2; it++) {
                int e = tid + it * 256;
                int k = e >> 3, g = e & 7;
                size_t off = (size_t)k * NPAD_ + n0 + g * 8;
                aph[it] = *(const uint4*)(aht + off);
                apl[it] = *(const uint4*)(alt + off);
            }
        }

#pragma unroll
        for (int ks = 0; ks < 4; ks++) {
            uint32_t Ah[2][4], Al[2][4], Bh[2][4], Bl[2][4];
#pragma unroll
            for (int mt = 0; mt < 2; mt++) {
                int row = wm * 32 + mt * 16 + (lane & 15);
                uint32_t coff = (uint32_t)(ks * 16 + (lane >> 4) * 8) * 2;
                uint32_t adr = sb + VA_HI + row * 144 + coff;
                ldm_x4(Ah[mt], adr);
                ldm_x4(Al[mt], adr + (VA_LO - VA_HI));
            }
#pragma unroll
            for (int bp = 0; bp < 2; bp++) {
                int crow = wn * 32 + bp * 16 + ((lane >> 4) << 3) + (lane & 7);
                uint32_t coff = (uint32_t)(ks * 16 + ((lane >> 3) & 1) * 8) * 2;
                uint32_t adr = sb + VB_HI + crow * 144 + coff;
                ldm_x4(Bh[bp], adr);
                ldm_x4(Bl[bp], adr + (VB_LO - VB_HI));
            }
#pragma unroll
            for (int mt = 0; mt < 2; mt++) {
#pragma unroll
                for (int nt = 0; nt < 4; nt++) {
                    int bp = nt >> 1, hp = (nt & 1) * 2;
                    float* dd = d[mt * 4 + nt];
                    mma_bf16(dd, Ah[mt], Bh[bp][hp], Bh[bp][hp + 1]);
                    mma_bf16(dd, Ah[mt], Bl[bp][hp], Bl[bp][hp + 1]);
                    mma_bf16(dd, Al[mt], Bh[bp][hp], Bh[bp][hp + 1]);
                }
            }
        }

        if (ch < 12) {
            __syncthreads();
#pragma unroll
            for (int it = 0; it < 4; it++) {
                int e = tid + it * 256;
                int r = e >> 3, g = e & 7;
                float4 f0 = xp[it*2], f1 = xp[it*2+1];
                float vv[8] = {f0.x,f0.y,f0.z,f0.w,f1.x,f1.y,f1.z,f1.w};
                unsigned short hh[8], ll[8];
#pragma unroll
                for (int q = 0; q < 8; q++) bsplit(vv[q], hh[q], ll[q]);
                uint4 uh, ul;
                uh.x = hh[0] | ((uint32_t)hh[1] << 16); uh.y = hh[2] | ((uint32_t)hh[3] << 16);
                uh.z = hh[4] | ((uint32_t)hh[5] << 16); uh.w = hh[6] | ((uint32_t)hh[7] << 16);
                ul.x = ll[0] | ((uint32_t)ll[1] << 16); ul.y = ll[2] | ((uint32_t)ll[3] << 16);
                ul.z = ll[4] | ((uint32_t)ll[5] << 16); ul.w = ll[6] | ((uint32_t)ll[7] << 16);
                *(uint4*)(sm + VB_HI + r * 144 + g * 16) = uh;
                *(uint4*)(sm + VB_LO + r * 144 + g * 16) = ul;
            }
#pragma unroll
            for (int it = 0; it < 2; it++) {
                int e = tid + it * 256;
                int k = e >> 3, g = e & 7;
                *(uint4*)(sm + VA_HI + k * 144 + g * 16) = aph[it];
                *(uint4*)(sm + VA_LO + k * 144 + g * 16) = apl[it];
            }
            __syncthreads();
        }
    }

#pragma unroll
    for (int mt = 0; mt < 2; mt++) {
#pragma unroll
        for (int nt = 0; nt < 4; nt++) {
            float* dd = d[mt * 4 + nt];
            int k = wm * 32 + mt * 16 + (lane >> 2);
            int c = c0 + wn * 32 + nt * 8 + (lane & 3) * 2;
            *(float2*)&g_vlad[(size_t)(t * K_ + k) * C_ + c]     = make_float2(dd[0], dd[1]);
            *(float2*)&g_vlad[(size_t)(t * K_ + k + 8) * C_ + c] = make_float2(dd[2], dd[3]);
        }
    }
}

// ---------------- pass 3: per-row scalars only (as, sc, ssn) — NO vlad writeback ----------------
// grid T*K/4 = 480, block 128 (warp per (t,k) row)
__global__ __launch_bounds__(128) void scal_kernel(const float* __restrict__ cent) {
    const int warp = threadIdx.x >> 5;
    const int lane = threadIdx.x & 31;
    const int row  = blockIdx.x * 4 + warp;
    const int t = row >> 6, k = row & 63;

    float as = 0.f;
#pragma unroll
    for (int b = 0; b < NB_; b++)
        as += g_asump[((size_t)t * NB_ + b) * K_ + k];

    const size_t base4 = (size_t)row * (C_ / 4);
    const float4* A = (const float4*)g_vlad;
    const float4* CW = (const float4*)cent;

    float ss = 0.f;
#pragma unroll
    for (int q = 0; q < 4; q++) {
        int idx = q * 32 + lane;
        float4 a = A[base4 + idx];
        float4 cw = CW[(size_t)k * (C_ / 4) + idx];
        float vx = a.x - as * cw.x;
        float vy = a.y - as * cw.y;
        float vz = a.z - as * cw.z;
        float vw = a.w - as * cw.w;
        ss += vx * vx + vy * vy + vz * vz + vw * vw;
    }
#pragma unroll
    for (int o = 16; o; o >>= 1) ss += __shfl_xor_sync(0xffffffff, ss, o);
    if (lane == 0) {
        float sc = 1.f / fmaxf(sqrtf(ss), 1e-12f);
        g_scv[row] = sc;
        g_asv[row] = as;
        g_ssn[row] = ss * sc * sc;
    }
}

// ---------------- pass 4: fused global-normalize + intra-norm-apply + sum over t ----------------
// out[i=k*512+c] = Σ_t vlad[t][i]·A[t,k] − cent[i]·SB[k],  A = sc·gsc, SB = Σ_t as·A
__global__ __launch_bounds__(256) void finalize_kernel(
    float* __restrict__ out, const float* __restrict__ cent)
{
    __shared__ float sA[T_ * K_];     // becomes A[t][k]
    __shared__ float sAs[T_ * K_];
    __shared__ float sGsc[T_];
    __shared__ float sSB[K_];
    const int tid = threadIdx.x;

    for (int i = tid; i < T_ * K_; i += 256) {
        sA[i]  = g_ssn[i];            // temp: ssn
        sAs[i] = g_asv[i];
    }
    __syncthreads();
    if (tid < T_) {
        float s = 0.f;
#pragma unroll 8
        for (int q = 0; q < K_; q++) s += sA[tid * K_ + q];
        sGsc[tid] = 1.f / fmaxf(sqrtf(s), 1e-12f);
    }
    __syncthreads();
    for (int i = tid; i < T_ * K_; i += 256)
        sA[i] = g_scv[i] * sGsc[i >> 6];
    __syncthreads();
    if (tid < K_) {
        float sb = 0.f;
#pragma unroll
        for (int t = 0; t < T_; t++)
            sb += sAs[t * K_ + tid] * sA[t * K_ + tid];
        sSB[tid] = sb;
    }
    __syncthreads();

    const int i = blockIdx.x * 256 + tid;
    const int k = i >> 9;
    float s = 0.f;
#pragma unroll
    for (int t = 0; t < T_; t++)
        s += g_vlad[(size_t)t * KD_ + i] * sA[t * K_ + k];
    out[i] = s - cent[i] * sSB[k];
}

// ---------------- launch ----------------
extern "C" void kernel_launch(void* const* d_in, const int* in_sizes, int n_in,
                              void* d_out, int out_size) {
    const float* x1     = (const float*)d_in[0];   // [30,512,28,28]
    const float* cent   = (const float*)d_in[1];   // [64,512]
    const float* conv_w = (const float*)d_in[2];   // [64,512]
    const float* conv_b = (const float*)d_in[3];   // [64]
    float* out = (float*)d_out;                    // [1, 32768]

    cudaFuncSetAttribute(assign_kernel, cudaFuncAttributeMaxDynamicSharedMemorySize, A_SMEM);
    cudaFuncSetAttribute(vlad_kernel,   cudaFuncAttributeMaxDynamicSharedMemorySize, V_SMEM);

    prep_kernel<<<128, 256>>>(conv_w);
    {
        dim3 g(NB_, T_);
        assign_kernel<<<g, 128, A_SMEM>>>(x1, conv_b);
    }
    {
        dim3 g(C_ / 128, T_);
        vlad_kernel<<<g, 256, V_SMEM>>>(x1);
    }
    scal_kernel<<<(T_ * K_) / 4, 128>>>(cent);
    finalize_kernel<<<KD_ / 256, 256>>>(out, cent);
}